// round 12
// baseline (speedup 1.0000x reference)
#include <cuda_runtime.h>
#include <math.h>
#include <stdint.h>

#define NN 50000
#define EE 400000
#define HD 256
#define EPS 1e-5f

// ---------------- scratch (device globals, referenced BY NAME in device code) ----------------
__device__ __align__(16) float g_dinv[NN];                  // deg -> rsqrt(deg)
__device__ __align__(16) float g_buf1[(size_t)NN * HD];     // xw1 , then t (=h1@W2)
__device__ __align__(16) float g_buf2[(size_t)NN * HD];     // agg1
__device__ __align__(16) float g_buf3[(size_t)NN * HD];     // agg2 (h2 = relu(buf3) on the fly)
__device__ __align__(16) float g_AB[(size_t)NN * 512];      // [A | B] per node for edge MLP
__device__ __align__(16) float g_stats[512];                // per-channel sum, sumsq
__device__ __align__(16) float g_scale[HD];
__device__ __align__(16) float g_shift[HD];

__device__ __forceinline__ float* buf_sel(int s) {          // 1->buf1, 2->buf2, 3->AB, 4->buf3
    return s == 1 ? g_buf1 : (s == 2 ? g_buf2 : (s == 4 ? g_buf3 : g_AB));
}

// ---------------- small kernels ----------------
__global__ void k_init(int n) {
    int i = blockIdx.x * blockDim.x + threadIdx.x;
    if (i < n) g_dinv[i] = 1.0f;         // self loop contributes 1 to degree
    if (i < 512) g_stats[i] = 0.0f;
}

__global__ void k_deg_edges(const int* __restrict__ dst, int e) {
    int i = blockIdx.x * blockDim.x + threadIdx.x;
    if (i < e) atomicAdd(&g_dinv[dst[i]], 1.0f);
}

__global__ void k_dinv(int n) {
    int i = blockIdx.x * blockDim.x + threadIdx.x;
    if (i < n) g_dinv[i] = rsqrtf(g_dinv[i]);
}

// per edge: agg[dst,:] += xw[src,:] * dinv[src]*dinv[dst]   (64 threads/edge, RED.128)
__global__ void k_edge_agg(const int* __restrict__ src, const int* __restrict__ dst,
                           int xw_sel, int agg_sel, int e) {
    int t = blockIdx.x * blockDim.x + threadIdx.x;
    int ei = t >> 6;
    if (ei >= e) return;
    const float* xw = buf_sel(xw_sel);
    float* agg      = buf_sel(agg_sel);
    int q = (t & 63) << 2;
    int s = src[ei], d = dst[ei];
    float c = g_dinv[s] * g_dinv[d];
    float4 v = *(const float4*)(xw + (size_t)s * HD + q);
    v.x *= c; v.y *= c; v.z *= c; v.w *= c;
#if __CUDA_ARCH__ >= 900
    atomicAdd((float4*)(agg + (size_t)d * HD + q), v);
#else
    float* p = agg + (size_t)d * HD + q;
    atomicAdd(p + 0, v.x); atomicAdd(p + 1, v.y);
    atomicAdd(p + 2, v.z); atomicAdd(p + 3, v.w);
#endif
}

__global__ void k_bn_stats(int n) {                          // reads buf2
    int c = threadIdx.x;                                     // 256 channels
    float s = 0.f, s2 = 0.f;
    for (int r = blockIdx.x; r < n; r += gridDim.x) {
        float v = g_buf2[(size_t)r * HD + c];
        s += v; s2 += v * v;
    }
    atomicAdd(&g_stats[c], s);
    atomicAdd(&g_stats[HD + c], s2);
}

__global__ void k_bn_finalize(const float* __restrict__ gamma, const float* __restrict__ beta, int n) {
    int c = threadIdx.x;
    float inv_n = 1.0f / (float)n;
    float mu = g_stats[c] * inv_n;
    float var = g_stats[HD + c] * inv_n - mu * mu;
    float sc = gamma[c] * rsqrtf(var + EPS);
    g_scale[c] = sc;
    g_shift[c] = beta[c] - mu * sc;
}

// ---------------- 3xTF32 tensor-core GEMM, double-buffered, hi/lo-interleaved smem ----------------
__device__ __forceinline__ void cvt_hilo(float x, uint32_t& hi, uint32_t& lo) {
    uint32_t h;
    asm("cvt.rna.tf32.f32 %0, %1;" : "=r"(h) : "f"(x));
    float l = x - __uint_as_float(h);
    uint32_t lw;
    asm("cvt.rna.tf32.f32 %0, %1;" : "=r"(lw) : "f"(l));
    hi = h; lo = lw;
}

#define MMA_TF32(c, a0, a1, a2, a3, b0, b1)                                   \
    asm volatile("mma.sync.aligned.m16n8k8.row.col.f32.tf32.tf32.f32 "        \
                 "{%0,%1,%2,%3}, {%4,%5,%6,%7}, {%8,%9}, {%0,%1,%2,%3};"      \
                 : "+f"(c[0]), "+f"(c[1]), "+f"(c[2]), "+f"(c[3])             \
                 : "r"(a0), "r"(a1), "r"(a2), "r"(a3), "r"(b0), "r"(b1))

// A-load transform: 0 = none, 1 = relu, 2 = bn(scale,shift)+relu (per-column = k index)
__device__ __forceinline__ float4 a_transform(float4 v, int kcol, int a_mode) {
    if (a_mode == 1) {
        v.x = fmaxf(v.x, 0.f); v.y = fmaxf(v.y, 0.f);
        v.z = fmaxf(v.z, 0.f); v.w = fmaxf(v.w, 0.f);
    } else if (a_mode == 2) {
        v.x = fmaxf(fmaf(v.x, g_scale[kcol + 0], g_shift[kcol + 0]), 0.f);
        v.y = fmaxf(fmaf(v.y, g_scale[kcol + 1], g_shift[kcol + 1]), 0.f);
        v.z = fmaxf(fmaf(v.z, g_scale[kcol + 2], g_shift[kcol + 2]), 0.f);
        v.w = fmaxf(fmaf(v.w, g_scale[kcol + 3], g_shift[kcol + 3]), 0.f);
    }
    return v;
}

// pack two tf32 pairs into uint4 {h0,l0,h1,l1}
__device__ __forceinline__ uint4 pack2(float x, float y) {
    uint4 r;
    cvt_hilo(x, r.x, r.y);
    cvt_hilo(y, r.z, r.w);
    return r;
}

// C[M,*] = f(A)[M,K] @ B[K,ldb], fp32 via 3xTF32 (Ah*Bh + Ah*Bl + Al*Bh).
// Smem holds uint2{hi,lo} per element: one LDS.64 per fragment operand pair.
__global__ __launch_bounds__(256, 2) void k_gemm(const float* __restrict__ Aext, int a_sel, int a_mode,
                                                 const float* __restrict__ B,
                                                 int c_sel, int c_off, int ldc,
                                                 int agg_sel, const float* __restrict__ bias,
                                                 int M, int K, int ldb) {
    const int BM = 128, BN = 64, BK = 16;
    const int SA = BK + 4;   // 20 uint2-stride: phase bank 8*gq+2*tig, conflict-free
    const int SB = BN + 4;   // 68 uint2-stride: 68%16==4 -> phase bank 8*tig+2*gq, conflict-free
    __shared__ __align__(16) uint2 As[2][BM][SA];
    __shared__ __align__(16) uint2 Bs[2][BK][SB];

    const float* A = (a_sel == 0) ? Aext : buf_sel(a_sel);
    float* C = buf_sel(c_sel) + c_off;

    int tid = threadIdx.x;
    int m0 = blockIdx.y * BM;
    int n0 = blockIdx.x * BN;

    int a_r = tid >> 2;              // 0..63 (rows a_r and a_r+64)
    int a_c = (tid & 3) << 2;        // 0,4,8,12 (k group of 4)
    int b_r = tid >> 4;              // 0..15 (k)
    int b_c = (tid & 15) << 2;       // 0..60 (n group of 4)

    int wid = tid >> 5, lane = tid & 31;
    int mbase = (wid & 3) * 32;
    int nbase = (wid >> 2) * 32;
    int gq = lane >> 2, tig = lane & 3;

    float acc[2][4][4];
#pragma unroll
    for (int mi = 0; mi < 2; mi++)
#pragma unroll
        for (int nj = 0; nj < 4; nj++)
#pragma unroll
            for (int r = 0; r < 4; r++) acc[mi][nj][r] = 0.f;

    int r0g = m0 + a_r, r1g = m0 + a_r + 64;

    // prologue: tile 0 -> smem buf 0
    {
        float4 va0 = (r0g < M) ? a_transform(*(const float4*)(A + (size_t)r0g * K + a_c), a_c, a_mode)
                               : make_float4(0,0,0,0);
        float4 va1 = (r1g < M) ? a_transform(*(const float4*)(A + (size_t)r1g * K + a_c), a_c, a_mode)
                               : make_float4(0,0,0,0);
        float4 vb  = *(const float4*)(B + (size_t)b_r * ldb + n0 + b_c);
        *(uint4*)&As[0][a_r][a_c]          = pack2(va0.x, va0.y);
        *(uint4*)&As[0][a_r][a_c + 2]      = pack2(va0.z, va0.w);
        *(uint4*)&As[0][a_r + 64][a_c]     = pack2(va1.x, va1.y);
        *(uint4*)&As[0][a_r + 64][a_c + 2] = pack2(va1.z, va1.w);
        *(uint4*)&Bs[0][b_r][b_c]          = pack2(vb.x, vb.y);
        *(uint4*)&Bs[0][b_r][b_c + 2]      = pack2(vb.z, vb.w);
    }
    __syncthreads();

    int KT = K / BK;
    for (int kt = 0; kt < KT; kt++) {
        int cur = kt & 1, nxt = cur ^ 1;

        float4 va0, va1, vb;
        bool have_next = (kt + 1 < KT);
        if (have_next) {
            int k0g = (kt + 1) * BK;
            va0 = (r0g < M) ? a_transform(*(const float4*)(A + (size_t)r0g * K + k0g + a_c), k0g + a_c, a_mode)
                            : make_float4(0,0,0,0);
            va1 = (r1g < M) ? a_transform(*(const float4*)(A + (size_t)r1g * K + k0g + a_c), k0g + a_c, a_mode)
                            : make_float4(0,0,0,0);
            vb  = *(const float4*)(B + (size_t)(k0g + b_r) * ldb + n0 + b_c);
        }

        // compute on buffer `cur` — one LDS.64 per operand pair
#pragma unroll
        for (int ks = 0; ks < 2; ks++) {
            int k0 = ks * 8;
            uint2 a01[2][4];   // [mi][frag]: {hi,lo} for a0..a3
#pragma unroll
            for (int mi = 0; mi < 2; mi++) {
                int r = mbase + mi * 16 + gq;
                a01[mi][0] = As[cur][r][k0 + tig];
                a01[mi][1] = As[cur][r + 8][k0 + tig];
                a01[mi][2] = As[cur][r][k0 + tig + 4];
                a01[mi][3] = As[cur][r + 8][k0 + tig + 4];
            }
#pragma unroll
            for (int nj = 0; nj < 4; nj++) {
                int cn = nbase + nj * 8 + gq;
                uint2 b0 = Bs[cur][k0 + tig][cn];
                uint2 b1 = Bs[cur][k0 + tig + 4][cn];
#pragma unroll
                for (int mi = 0; mi < 2; mi++) {
                    MMA_TF32(acc[mi][nj], a01[mi][0].x, a01[mi][1].x, a01[mi][2].x, a01[mi][3].x, b0.x, b1.x);
                    MMA_TF32(acc[mi][nj], a01[mi][0].x, a01[mi][1].x, a01[mi][2].x, a01[mi][3].x, b0.y, b1.y);
                    MMA_TF32(acc[mi][nj], a01[mi][0].y, a01[mi][1].y, a01[mi][2].y, a01[mi][3].y, b0.x, b1.x);
                }
            }
        }

        if (have_next) {
            *(uint4*)&As[nxt][a_r][a_c]          = pack2(va0.x, va0.y);
            *(uint4*)&As[nxt][a_r][a_c + 2]      = pack2(va0.z, va0.w);
            *(uint4*)&As[nxt][a_r + 64][a_c]     = pack2(va1.x, va1.y);
            *(uint4*)&As[nxt][a_r + 64][a_c + 2] = pack2(va1.z, va1.w);
            *(uint4*)&Bs[nxt][b_r][b_c]          = pack2(vb.x, vb.y);
            *(uint4*)&Bs[nxt][b_r][b_c + 2]      = pack2(vb.z, vb.w);
            __syncthreads();
        }
    }

    float* Cagg = agg_sel ? buf_sel(agg_sel) : nullptr;
#pragma unroll
    for (int mi = 0; mi < 2; mi++) {
#pragma unroll
        for (int nj = 0; nj < 4; nj++) {
            int row0 = m0 + mbase + mi * 16 + gq;
            int col  = n0 + nbase + nj * 8 + tig * 2;
#pragma unroll
            for (int h = 0; h < 2; h++) {
                int r = row0 + h * 8;
                if (r >= M) continue;
                float vx = acc[mi][nj][h * 2], vy = acc[mi][nj][h * 2 + 1];
                float2 v = make_float2(vx, vy);
                *(float2*)(C + (size_t)r * ldc + col) = v;
                if (agg_sel) {
                    float dv = g_dinv[r]; dv *= dv;
                    float2 w;
                    w.x = fmaf(vx, dv, bias[col]);
                    w.y = fmaf(vy, dv, bias[col + 1]);
                    *(float2*)(Cagg + (size_t)r * HD + col) = w;
                }
            }
        }
    }
}

// ---------------- edge MLP: out[e] = sigmoid( relu(AB_A[s]+AB_B[d]+bm1) . Wm2 + bm2 ) ----------------
__global__ __launch_bounds__(256) void k_edge_mlp(const int* __restrict__ src,
                                                  const int* __restrict__ dst,
                                                  const float* __restrict__ bm1,
                                                  const float* __restrict__ Wm2,
                                                  const float* __restrict__ bm2,
                                                  float* __restrict__ out, int e) {
    __shared__ __align__(16) float w[HD];
    __shared__ __align__(16) float b[HD];
    int tid = threadIdx.x;
    w[tid] = Wm2[tid];
    b[tid] = bm1[tid];
    __syncthreads();
    int ei = blockIdx.x * 8 + (tid >> 5);
    if (ei >= e) return;
    int lane = tid & 31;
    int s = src[ei], d = dst[ei];
    const float* pa = g_AB + (size_t)s * 512;
    const float* pb = g_AB + (size_t)d * 512 + HD;
    float acc = 0.f;
#pragma unroll
    for (int it = 0; it < 2; it++) {
        int j = (it * 32 + lane) << 2;
        float4 va = *(const float4*)(pa + j);
        float4 vb = *(const float4*)(pb + j);
        float4 vbi = *(const float4*)(b + j);
        float4 vw = *(const float4*)(w + j);
        acc += fmaxf(va.x + vb.x + vbi.x, 0.f) * vw.x;
        acc += fmaxf(va.y + vb.y + vbi.y, 0.f) * vw.y;
        acc += fmaxf(va.z + vb.z + vbi.z, 0.f) * vw.z;
        acc += fmaxf(va.w + vb.w + vbi.w, 0.f) * vw.w;
    }
#pragma unroll
    for (int o = 16; o; o >>= 1) acc += __shfl_xor_sync(0xffffffffu, acc, o);
    if (lane == 0) {
        float z = acc + bm2[0];
        out[ei] = 1.0f / (1.0f + expf(-z));
    }
}

// ---------------- launch ----------------
extern "C" void kernel_launch(void* const* d_in, const int* in_sizes, int n_in,
                              void* d_out, int out_size) {
    const float* x    = (const float*)d_in[0];
    const int*   ei   = (const int*)d_in[1];     // edge_index delivered as int32
    const float* W1   = (const float*)d_in[2];
    const float* b1   = (const float*)d_in[3];
    const float* gamma= (const float*)d_in[4];
    const float* beta = (const float*)d_in[5];
    const float* W2   = (const float*)d_in[6];
    const float* b2   = (const float*)d_in[7];
    const float* Wm1  = (const float*)d_in[8];
    const float* bm1  = (const float*)d_in[9];
    const float* Wm2  = (const float*)d_in[10];
    const float* bm2  = (const float*)d_in[11];
    float* out = (float*)d_out;

    const int n = in_sizes[0] / 128;      // 50000
    const int e = in_sizes[1] / 2;        // 400000
    const int* src = ei;
    const int* dst = ei + e;

    // 1. degrees / norm
    k_init<<<(n + 255) / 256, 256>>>(n);
    k_deg_edges<<<(e + 255) / 256, 256>>>(dst, e);
    k_dinv<<<(n + 255) / 256, 256>>>(n);

    dim3 g1(HD / 64, (n + 127) / 128);    // 4 x 391

    // 2. gcn1: buf1 = x@W1, fused agg-init -> buf2 ; edge agg buf1 -> buf2
    k_gemm<<<g1, 256>>>(x, 0, 0, W1, 1, 0, HD, 2, b1, n, 128, HD);
    k_edge_agg<<<(e * 64 + 255) / 256, 256>>>(src, dst, 1, 2, e);

    // 3. batchnorm stats (apply is fused into the next GEMM's A-load)
    k_bn_stats<<<512, 256>>>(n);
    k_bn_finalize<<<1, 256>>>(gamma, beta, n);

    // 4. gcn2: buf1 = bn_relu(buf2)@W2, fused agg-init -> buf3 ; edge agg buf1 -> buf3
    k_gemm<<<g1, 256>>>(nullptr, 2, 2, W2, 1, 0, HD, 4, b2, n, HD, HD);
    k_edge_agg<<<(e * 64 + 255) / 256, 256>>>(src, dst, 1, 4, e);

    // 5. hoisted MLP layer 1 (relu fused into A-load):
    //    AB[:,0:256] = relu(buf3)@Wm1_top, AB[:,256:512] = relu(buf3)@Wm1_bot
    k_gemm<<<g1, 256>>>(nullptr, 4, 1, Wm1,            3, 0,  512, 0, nullptr, n, HD, HD);
    k_gemm<<<g1, 256>>>(nullptr, 4, 1, Wm1 + 256 * HD, 3, HD, 512, 0, nullptr, n, HD, HD);

    // 6. per-edge epilogue
    k_edge_mlp<<<(e + 7) / 8, 256>>>(src, dst, bm1, Wm2, bm2, out, e);
}

// round 13
// speedup vs baseline: 1.1055x; 1.1055x over previous
#include <cuda_runtime.h>
#include <math.h>
#include <stdint.h>

#define NN 50000
#define EE 400000
#define HD 256
#define EPS 1e-5f

// ---------------- scratch (device globals, referenced BY NAME in device code) ----------------
__device__ __align__(16) float g_dinv[NN];                  // deg -> rsqrt(deg)
__device__ __align__(16) float g_buf1[(size_t)NN * HD];     // xw1 , then t (=h1@W2)
__device__ __align__(16) float g_buf2[(size_t)NN * HD];     // agg1
__device__ __align__(16) float g_buf3[(size_t)NN * HD];     // agg2 (h2 = relu(buf3) on the fly)
__device__ __align__(16) float g_AB[(size_t)NN * 512];      // [A | B] per node for edge MLP
__device__ __align__(16) float g_stats[512];                // per-channel sum, sumsq
__device__ __align__(16) float g_scale[HD];
__device__ __align__(16) float g_shift[HD];

__device__ __forceinline__ float* buf_sel(int s) {          // 1->buf1, 2->buf2, 3->AB, 4->buf3
    return s == 1 ? g_buf1 : (s == 2 ? g_buf2 : (s == 4 ? g_buf3 : g_AB));
}

// ---------------- small kernels ----------------
__global__ void k_init(int n) {
    int i = blockIdx.x * blockDim.x + threadIdx.x;
    if (i < n) g_dinv[i] = 1.0f;         // self loop contributes 1 to degree
    if (i < 512) g_stats[i] = 0.0f;
}

__global__ void k_deg_edges(const int* __restrict__ dst, int e) {
    int i = blockIdx.x * blockDim.x + threadIdx.x;
    if (i < e) atomicAdd(&g_dinv[dst[i]], 1.0f);
}

__global__ void k_dinv(int n) {
    int i = blockIdx.x * blockDim.x + threadIdx.x;
    if (i < n) g_dinv[i] = rsqrtf(g_dinv[i]);
}

// per edge: agg[dst,:] += xw[src,:] * dinv[src]*dinv[dst]   (64 threads/edge, RED.128)
__global__ void k_edge_agg(const int* __restrict__ src, const int* __restrict__ dst,
                           int xw_sel, int agg_sel, int e) {
    int t = blockIdx.x * blockDim.x + threadIdx.x;
    int ei = t >> 6;
    if (ei >= e) return;
    const float* xw = buf_sel(xw_sel);
    float* agg      = buf_sel(agg_sel);
    int q = (t & 63) << 2;
    int s = src[ei], d = dst[ei];
    float c = g_dinv[s] * g_dinv[d];
    float4 v = *(const float4*)(xw + (size_t)s * HD + q);
    v.x *= c; v.y *= c; v.z *= c; v.w *= c;
#if __CUDA_ARCH__ >= 900
    atomicAdd((float4*)(agg + (size_t)d * HD + q), v);
#else
    float* p = agg + (size_t)d * HD + q;
    atomicAdd(p + 0, v.x); atomicAdd(p + 1, v.y);
    atomicAdd(p + 2, v.z); atomicAdd(p + 3, v.w);
#endif
}

__global__ void k_bn_stats(int n) {                          // reads buf2
    int c = threadIdx.x;                                     // 256 channels
    float s = 0.f, s2 = 0.f;
    for (int r = blockIdx.x; r < n; r += gridDim.x) {
        float v = g_buf2[(size_t)r * HD + c];
        s += v; s2 += v * v;
    }
    atomicAdd(&g_stats[c], s);
    atomicAdd(&g_stats[HD + c], s2);
}

__global__ void k_bn_finalize(const float* __restrict__ gamma, const float* __restrict__ beta, int n) {
    int c = threadIdx.x;
    float inv_n = 1.0f / (float)n;
    float mu = g_stats[c] * inv_n;
    float var = g_stats[HD + c] * inv_n - mu * mu;
    float sc = gamma[c] * rsqrtf(var + EPS);
    g_scale[c] = sc;
    g_shift[c] = beta[c] - mu * sc;
}

// ---------------- TF32 tensor-core GEMM, double-buffered (passes = 3: full 3xTF32; 1: fast) ----------------
__device__ __forceinline__ void cvt_hilo(float x, uint32_t& hi, uint32_t& lo) {
    uint32_t h;
    asm("cvt.rna.tf32.f32 %0, %1;" : "=r"(h) : "f"(x));
    float l = x - __uint_as_float(h);
    uint32_t lw;
    asm("cvt.rna.tf32.f32 %0, %1;" : "=r"(lw) : "f"(l));
    hi = h; lo = lw;
}

__device__ __forceinline__ uint32_t cvt_hi(float x) {
    uint32_t h;
    asm("cvt.rna.tf32.f32 %0, %1;" : "=r"(h) : "f"(x));
    return h;
}

#define MMA_TF32(c, a0, a1, a2, a3, b0, b1)                                   \
    asm volatile("mma.sync.aligned.m16n8k8.row.col.f32.tf32.tf32.f32 "        \
                 "{%0,%1,%2,%3}, {%4,%5,%6,%7}, {%8,%9}, {%0,%1,%2,%3};"      \
                 : "+f"(c[0]), "+f"(c[1]), "+f"(c[2]), "+f"(c[3])             \
                 : "r"(a0), "r"(a1), "r"(a2), "r"(a3), "r"(b0), "r"(b1))

// A-load transform: 0 = none, 1 = relu, 2 = bn(scale,shift)+relu (per-column = k index)
__device__ __forceinline__ float4 a_transform(float4 v, int kcol, int a_mode) {
    if (a_mode == 1) {
        v.x = fmaxf(v.x, 0.f); v.y = fmaxf(v.y, 0.f);
        v.z = fmaxf(v.z, 0.f); v.w = fmaxf(v.w, 0.f);
    } else if (a_mode == 2) {
        v.x = fmaxf(fmaf(v.x, g_scale[kcol + 0], g_shift[kcol + 0]), 0.f);
        v.y = fmaxf(fmaf(v.y, g_scale[kcol + 1], g_shift[kcol + 1]), 0.f);
        v.z = fmaxf(fmaf(v.z, g_scale[kcol + 2], g_shift[kcol + 2]), 0.f);
        v.w = fmaxf(fmaf(v.w, g_scale[kcol + 3], g_shift[kcol + 3]), 0.f);
    }
    return v;
}

// C[M,*] = f(A)[M,K] @ B[K,ldb].  passes=3: fp32-accurate 3xTF32; passes=1: plain TF32.
__global__ __launch_bounds__(256, 2) void k_gemm(const float* __restrict__ Aext, int a_sel, int a_mode,
                                                 int passes,
                                                 const float* __restrict__ B,
                                                 int c_sel, int c_off, int ldc,
                                                 int agg_sel, const float* __restrict__ bias,
                                                 int M, int K, int ldb) {
    const int BM = 128, BN = 64, BK = 16;
    const int SA = BK + 4;   // 20
    const int SB = BN + 8;   // 72
    __shared__ __align__(16) uint32_t As_hi[2][BM][SA], As_lo[2][BM][SA];
    __shared__ __align__(16) uint32_t Bs_hi[2][BK][SB], Bs_lo[2][BK][SB];

    const float* A = (a_sel == 0) ? Aext : buf_sel(a_sel);
    float* C = buf_sel(c_sel) + c_off;

    int tid = threadIdx.x;
    int m0 = blockIdx.y * BM;
    int n0 = blockIdx.x * BN;

    int a_r = tid >> 2;              // 0..63 (rows a_r and a_r+64)
    int a_c = (tid & 3) << 2;        // 0,4,8,12 (k group of 4)
    int b_r = tid >> 4;              // 0..15 (k)
    int b_c = (tid & 15) << 2;       // 0..60 (n group of 4)

    int wid = tid >> 5, lane = tid & 31;
    int mbase = (wid & 3) * 32;
    int nbase = (wid >> 2) * 32;
    int gq = lane >> 2, tig = lane & 3;

    float acc[2][4][4];
#pragma unroll
    for (int mi = 0; mi < 2; mi++)
#pragma unroll
        for (int nj = 0; nj < 4; nj++)
#pragma unroll
            for (int r = 0; r < 4; r++) acc[mi][nj][r] = 0.f;

    int r0g = m0 + a_r, r1g = m0 + a_r + 64;

    // tile store helper (macro to keep register use predictable)
#define STORE_TILE(BUF, VA0, VA1, VB)                                          \
    do {                                                                       \
        if (passes == 3) {                                                     \
            uint4 h, l;                                                        \
            cvt_hilo(VA0.x, h.x, l.x); cvt_hilo(VA0.y, h.y, l.y);              \
            cvt_hilo(VA0.z, h.z, l.z); cvt_hilo(VA0.w, h.w, l.w);              \
            *(uint4*)&As_hi[BUF][a_r][a_c] = h;  *(uint4*)&As_lo[BUF][a_r][a_c] = l; \
            cvt_hilo(VA1.x, h.x, l.x); cvt_hilo(VA1.y, h.y, l.y);              \
            cvt_hilo(VA1.z, h.z, l.z); cvt_hilo(VA1.w, h.w, l.w);              \
            *(uint4*)&As_hi[BUF][a_r + 64][a_c] = h;  *(uint4*)&As_lo[BUF][a_r + 64][a_c] = l; \
            cvt_hilo(VB.x, h.x, l.x); cvt_hilo(VB.y, h.y, l.y);                \
            cvt_hilo(VB.z, h.z, l.z); cvt_hilo(VB.w, h.w, l.w);                \
            *(uint4*)&Bs_hi[BUF][b_r][b_c] = h;  *(uint4*)&Bs_lo[BUF][b_r][b_c] = l; \
        } else {                                                               \
            uint4 h;                                                           \
            h.x = cvt_hi(VA0.x); h.y = cvt_hi(VA0.y);                          \
            h.z = cvt_hi(VA0.z); h.w = cvt_hi(VA0.w);                          \
            *(uint4*)&As_hi[BUF][a_r][a_c] = h;                                \
            h.x = cvt_hi(VA1.x); h.y = cvt_hi(VA1.y);                          \
            h.z = cvt_hi(VA1.z); h.w = cvt_hi(VA1.w);                          \
            *(uint4*)&As_hi[BUF][a_r + 64][a_c] = h;                           \
            h.x = cvt_hi(VB.x); h.y = cvt_hi(VB.y);                            \
            h.z = cvt_hi(VB.z); h.w = cvt_hi(VB.w);                            \
            *(uint4*)&Bs_hi[BUF][b_r][b_c] = h;                                \
        }                                                                      \
    } while (0)

    // prologue: tile 0 -> smem buf 0
    {
        float4 va0 = (r0g < M) ? a_transform(*(const float4*)(A + (size_t)r0g * K + a_c), a_c, a_mode)
                               : make_float4(0,0,0,0);
        float4 va1 = (r1g < M) ? a_transform(*(const float4*)(A + (size_t)r1g * K + a_c), a_c, a_mode)
                               : make_float4(0,0,0,0);
        float4 vb  = *(const float4*)(B + (size_t)b_r * ldb + n0 + b_c);
        STORE_TILE(0, va0, va1, vb);
    }
    __syncthreads();

    int KT = K / BK;
    for (int kt = 0; kt < KT; kt++) {
        int cur = kt & 1, nxt = cur ^ 1;

        float4 va0, va1, vb;
        bool have_next = (kt + 1 < KT);
        if (have_next) {
            int k0g = (kt + 1) * BK;
            va0 = (r0g < M) ? a_transform(*(const float4*)(A + (size_t)r0g * K + k0g + a_c), k0g + a_c, a_mode)
                            : make_float4(0,0,0,0);
            va1 = (r1g < M) ? a_transform(*(const float4*)(A + (size_t)r1g * K + k0g + a_c), k0g + a_c, a_mode)
                            : make_float4(0,0,0,0);
            vb  = *(const float4*)(B + (size_t)(k0g + b_r) * ldb + n0 + b_c);
        }

        // compute on buffer `cur`
#pragma unroll
        for (int ks = 0; ks < 2; ks++) {
            int k0 = ks * 8;
            uint32_t ah[2][4], al[2][4];
#pragma unroll
            for (int mi = 0; mi < 2; mi++) {
                int r = mbase + mi * 16 + gq;
                ah[mi][0] = As_hi[cur][r][k0 + tig];
                ah[mi][1] = As_hi[cur][r + 8][k0 + tig];
                ah[mi][2] = As_hi[cur][r][k0 + tig + 4];
                ah[mi][3] = As_hi[cur][r + 8][k0 + tig + 4];
                if (passes == 3) {
                    al[mi][0] = As_lo[cur][r][k0 + tig];
                    al[mi][1] = As_lo[cur][r + 8][k0 + tig];
                    al[mi][2] = As_lo[cur][r][k0 + tig + 4];
                    al[mi][3] = As_lo[cur][r + 8][k0 + tig + 4];
                }
            }
#pragma unroll
            for (int nj = 0; nj < 4; nj++) {
                int cn = nbase + nj * 8 + gq;
                uint32_t bh0 = Bs_hi[cur][k0 + tig][cn],     bh1 = Bs_hi[cur][k0 + tig + 4][cn];
#pragma unroll
                for (int mi = 0; mi < 2; mi++)
                    MMA_TF32(acc[mi][nj], ah[mi][0], ah[mi][1], ah[mi][2], ah[mi][3], bh0, bh1);
                if (passes == 3) {
                    uint32_t bl0 = Bs_lo[cur][k0 + tig][cn], bl1 = Bs_lo[cur][k0 + tig + 4][cn];
#pragma unroll
                    for (int mi = 0; mi < 2; mi++) {
                        MMA_TF32(acc[mi][nj], ah[mi][0], ah[mi][1], ah[mi][2], ah[mi][3], bl0, bl1);
                        MMA_TF32(acc[mi][nj], al[mi][0], al[mi][1], al[mi][2], al[mi][3], bh0, bh1);
                    }
                }
            }
        }

        if (have_next) {
            STORE_TILE(nxt, va0, va1, vb);
            __syncthreads();
        }
    }
#undef STORE_TILE

    float* Cagg = agg_sel ? buf_sel(agg_sel) : nullptr;
#pragma unroll
    for (int mi = 0; mi < 2; mi++) {
#pragma unroll
        for (int nj = 0; nj < 4; nj++) {
            int row0 = m0 + mbase + mi * 16 + gq;
            int col  = n0 + nbase + nj * 8 + tig * 2;
#pragma unroll
            for (int h = 0; h < 2; h++) {
                int r = row0 + h * 8;
                if (r >= M) continue;
                float vx = acc[mi][nj][h * 2], vy = acc[mi][nj][h * 2 + 1];
                float2 v = make_float2(vx, vy);
                *(float2*)(C + (size_t)r * ldc + col) = v;
                if (agg_sel) {
                    float dv = g_dinv[r]; dv *= dv;
                    float2 w;
                    w.x = fmaf(vx, dv, bias[col]);
                    w.y = fmaf(vy, dv, bias[col + 1]);
                    *(float2*)(Cagg + (size_t)r * HD + col) = w;
                }
            }
        }
    }
}

// ---------------- edge MLP: out[e] = sigmoid( relu(AB_A[s]+AB_B[d]+bm1) . Wm2 + bm2 ) ----------------
__global__ __launch_bounds__(256) void k_edge_mlp(const int* __restrict__ src,
                                                  const int* __restrict__ dst,
                                                  const float* __restrict__ bm1,
                                                  const float* __restrict__ Wm2,
                                                  const float* __restrict__ bm2,
                                                  float* __restrict__ out, int e) {
    __shared__ __align__(16) float w[HD];
    __shared__ __align__(16) float b[HD];
    int tid = threadIdx.x;
    w[tid] = Wm2[tid];
    b[tid] = bm1[tid];
    __syncthreads();
    int ei = blockIdx.x * 8 + (tid >> 5);
    if (ei >= e) return;
    int lane = tid & 31;
    int s = src[ei], d = dst[ei];
    const float* pa = g_AB + (size_t)s * 512;
    const float* pb = g_AB + (size_t)d * 512 + HD;
    float acc = 0.f;
#pragma unroll
    for (int it = 0; it < 2; it++) {
        int j = (it * 32 + lane) << 2;
        float4 va = *(const float4*)(pa + j);
        float4 vb = *(const float4*)(pb + j);
        float4 vbi = *(const float4*)(b + j);
        float4 vw = *(const float4*)(w + j);
        acc += fmaxf(va.x + vb.x + vbi.x, 0.f) * vw.x;
        acc += fmaxf(va.y + vb.y + vbi.y, 0.f) * vw.y;
        acc += fmaxf(va.z + vb.z + vbi.z, 0.f) * vw.z;
        acc += fmaxf(va.w + vb.w + vbi.w, 0.f) * vw.w;
    }
#pragma unroll
    for (int o = 16; o; o >>= 1) acc += __shfl_xor_sync(0xffffffffu, acc, o);
    if (lane == 0) {
        float z = acc + bm2[0];
        out[ei] = 1.0f / (1.0f + expf(-z));
    }
}

// ---------------- launch ----------------
extern "C" void kernel_launch(void* const* d_in, const int* in_sizes, int n_in,
                              void* d_out, int out_size) {
    const float* x    = (const float*)d_in[0];
    const int*   ei   = (const int*)d_in[1];     // edge_index delivered as int32
    const float* W1   = (const float*)d_in[2];
    const float* b1   = (const float*)d_in[3];
    const float* gamma= (const float*)d_in[4];
    const float* beta = (const float*)d_in[5];
    const float* W2   = (const float*)d_in[6];
    const float* b2   = (const float*)d_in[7];
    const float* Wm1  = (const float*)d_in[8];
    const float* bm1  = (const float*)d_in[9];
    const float* Wm2  = (const float*)d_in[10];
    const float* bm2  = (const float*)d_in[11];
    float* out = (float*)d_out;

    const int n = in_sizes[0] / 128;      // 50000
    const int e = in_sizes[1] / 2;        // 400000
    const int* src = ei;
    const int* dst = ei + e;

    // 1. degrees / norm
    k_init<<<(n + 255) / 256, 256>>>(n);
    k_deg_edges<<<(e + 255) / 256, 256>>>(dst, e);
    k_dinv<<<(n + 255) / 256, 256>>>(n);

    dim3 g1(HD / 64, (n + 127) / 128);    // 4 x 391

    // 2. gcn1: buf1 = x@W1 (3xTF32), fused agg-init -> buf2 ; edge agg buf1 -> buf2
    k_gemm<<<g1, 256>>>(x, 0, 0, 3, W1, 1, 0, HD, 2, b1, n, 128, HD);
    k_edge_agg<<<(e * 64 + 255) / 256, 256>>>(src, dst, 1, 2, e);

    // 3. batchnorm stats (apply is fused into the next GEMM's A-load)
    k_bn_stats<<<512, 256>>>(n);
    k_bn_finalize<<<1, 256>>>(gamma, beta, n);

    // 4. gcn2: buf1 = bn_relu(buf2)@W2 (3xTF32), fused agg-init -> buf3 ; edge agg buf1 -> buf3
    k_gemm<<<g1, 256>>>(nullptr, 2, 2, 3, W2, 1, 0, HD, 4, b2, n, HD, HD);
    k_edge_agg<<<(e * 64 + 255) / 256, 256>>>(src, dst, 1, 4, e);

    // 5. hoisted MLP layer 1 (relu fused into A-load, single-pass TF32 — last layer, error budget OK):
    k_gemm<<<g1, 256>>>(nullptr, 4, 1, 1, Wm1,            3, 0,  512, 0, nullptr, n, HD, HD);
    k_gemm<<<g1, 256>>>(nullptr, 4, 1, 1, Wm1 + 256 * HD, 3, HD, 512, 0, nullptr, n, HD, HD);

    // 6. per-edge epilogue
    k_edge_mlp<<<(e + 7) / 8, 256>>>(src, dst, bm1, Wm2, bm2, out, e);
}

// round 14
// speedup vs baseline: 1.1055x; 1.0000x over previous
#include <cuda_runtime.h>
#include <math.h>
#include <stdint.h>

#define NN 50000
#define EE 400000
#define HD 256
#define EPS 1e-5f

// ---------------- scratch (device globals, referenced BY NAME in device code) ----------------
__device__ __align__(16) float g_dinv[NN];                  // deg -> rsqrt(deg)
__device__ __align__(16) float g_buf1[(size_t)NN * HD];     // xw1 , then t (=h1@W2)
__device__ __align__(16) float g_buf2[(size_t)NN * HD];     // agg1
__device__ __align__(16) float g_buf3[(size_t)NN * HD];     // agg2 (h2 = relu(buf3) on the fly)
__device__ __align__(16) float g_AB[(size_t)NN * 512];      // [A | B] per node for edge MLP
__device__ __align__(16) float g_stats[512];                // per-channel sum, sumsq
__device__ __align__(16) float g_scale[HD];
__device__ __align__(16) float g_shift[HD];

__device__ __forceinline__ float* buf_sel(int s) {          // 1->buf1, 2->buf2, 3->AB, 4->buf3
    return s == 1 ? g_buf1 : (s == 2 ? g_buf2 : (s == 4 ? g_buf3 : g_AB));
}

// ---------------- small kernels ----------------
__global__ void k_init(int n) {
    int i = blockIdx.x * blockDim.x + threadIdx.x;
    if (i < n) g_dinv[i] = 1.0f;         // self loop contributes 1 to degree
    if (i < 512) g_stats[i] = 0.0f;
}

__global__ void k_deg_edges(const int* __restrict__ dst, int e) {
    int i = blockIdx.x * blockDim.x + threadIdx.x;
    if (i < e) atomicAdd(&g_dinv[dst[i]], 1.0f);
}

__global__ void k_dinv(int n) {
    int i = blockIdx.x * blockDim.x + threadIdx.x;
    if (i < n) g_dinv[i] = rsqrtf(g_dinv[i]);
}

// per edge: agg[dst,:] += xw[src,:] * dinv[src]*dinv[dst]   (64 threads/edge, RED.128)
__global__ void k_edge_agg(const int* __restrict__ src, const int* __restrict__ dst,
                           int xw_sel, int agg_sel, int e) {
    int t = blockIdx.x * blockDim.x + threadIdx.x;
    int ei = t >> 6;
    if (ei >= e) return;
    const float* xw = buf_sel(xw_sel);
    float* agg      = buf_sel(agg_sel);
    int q = (t & 63) << 2;
    int s = src[ei], d = dst[ei];
    float c = g_dinv[s] * g_dinv[d];
    float4 v = *(const float4*)(xw + (size_t)s * HD + q);
    v.x *= c; v.y *= c; v.z *= c; v.w *= c;
#if __CUDA_ARCH__ >= 900
    atomicAdd((float4*)(agg + (size_t)d * HD + q), v);
#else
    float* p = agg + (size_t)d * HD + q;
    atomicAdd(p + 0, v.x); atomicAdd(p + 1, v.y);
    atomicAdd(p + 2, v.z); atomicAdd(p + 3, v.w);
#endif
}

__global__ void k_bn_stats(int n) {                          // reads buf2
    int c = threadIdx.x;                                     // 256 channels
    float s = 0.f, s2 = 0.f;
    for (int r = blockIdx.x; r < n; r += gridDim.x) {
        float v = g_buf2[(size_t)r * HD + c];
        s += v; s2 += v * v;
    }
    atomicAdd(&g_stats[c], s);
    atomicAdd(&g_stats[HD + c], s2);
}

__global__ void k_bn_finalize(const float* __restrict__ gamma, const float* __restrict__ beta, int n) {
    int c = threadIdx.x;
    float inv_n = 1.0f / (float)n;
    float mu = g_stats[c] * inv_n;
    float var = g_stats[HD + c] * inv_n - mu * mu;
    float sc = gamma[c] * rsqrtf(var + EPS);
    g_scale[c] = sc;
    g_shift[c] = beta[c] - mu * sc;
}

// ---------------- TF32 tensor-core GEMM, double-buffered (passes = 3: full 3xTF32; 1: fast) ----------------
__device__ __forceinline__ void cvt_hilo(float x, uint32_t& hi, uint32_t& lo) {
    uint32_t h;
    asm("cvt.rna.tf32.f32 %0, %1;" : "=r"(h) : "f"(x));
    float l = x - __uint_as_float(h);
    uint32_t lw;
    asm("cvt.rna.tf32.f32 %0, %1;" : "=r"(lw) : "f"(l));
    hi = h; lo = lw;
}

__device__ __forceinline__ uint32_t cvt_hi(float x) {
    uint32_t h;
    asm("cvt.rna.tf32.f32 %0, %1;" : "=r"(h) : "f"(x));
    return h;
}

#define MMA_TF32(c, a0, a1, a2, a3, b0, b1)                                   \
    asm volatile("mma.sync.aligned.m16n8k8.row.col.f32.tf32.tf32.f32 "        \
                 "{%0,%1,%2,%3}, {%4,%5,%6,%7}, {%8,%9}, {%0,%1,%2,%3};"      \
                 : "+f"(c[0]), "+f"(c[1]), "+f"(c[2]), "+f"(c[3])             \
                 : "r"(a0), "r"(a1), "r"(a2), "r"(a3), "r"(b0), "r"(b1))

// A-load transform: 0 = none, 1 = relu, 2 = bn(scale,shift)+relu (per-column = k index)
__device__ __forceinline__ float4 a_transform(float4 v, int kcol, int a_mode) {
    if (a_mode == 1) {
        v.x = fmaxf(v.x, 0.f); v.y = fmaxf(v.y, 0.f);
        v.z = fmaxf(v.z, 0.f); v.w = fmaxf(v.w, 0.f);
    } else if (a_mode == 2) {
        v.x = fmaxf(fmaf(v.x, g_scale[kcol + 0], g_shift[kcol + 0]), 0.f);
        v.y = fmaxf(fmaf(v.y, g_scale[kcol + 1], g_shift[kcol + 1]), 0.f);
        v.z = fmaxf(fmaf(v.z, g_scale[kcol + 2], g_shift[kcol + 2]), 0.f);
        v.w = fmaxf(fmaf(v.w, g_scale[kcol + 3], g_shift[kcol + 3]), 0.f);
    }
    return v;
}

// C[M,*] = f(A)[M,K] @ B[K,ldb].  passes=3: fp32-accurate 3xTF32; passes=1: plain TF32.
__global__ __launch_bounds__(256, 2) void k_gemm(const float* __restrict__ Aext, int a_sel, int a_mode,
                                                 int passes,
                                                 const float* __restrict__ B,
                                                 int c_sel, int c_off, int ldc,
                                                 int agg_sel, const float* __restrict__ bias,
                                                 int M, int K, int ldb) {
    const int BM = 128, BN = 64, BK = 16;
    const int SA = BK + 4;   // 20
    const int SB = BN + 8;   // 72
    __shared__ __align__(16) uint32_t As_hi[2][BM][SA], As_lo[2][BM][SA];
    __shared__ __align__(16) uint32_t Bs_hi[2][BK][SB], Bs_lo[2][BK][SB];

    const float* A = (a_sel == 0) ? Aext : buf_sel(a_sel);
    float* C = buf_sel(c_sel) + c_off;

    int tid = threadIdx.x;
    int m0 = blockIdx.y * BM;
    int n0 = blockIdx.x * BN;

    int a_r = tid >> 2;              // 0..63 (rows a_r and a_r+64)
    int a_c = (tid & 3) << 2;        // 0,4,8,12 (k group of 4)
    int b_r = tid >> 4;              // 0..15 (k)
    int b_c = (tid & 15) << 2;       // 0..60 (n group of 4)

    int wid = tid >> 5, lane = tid & 31;
    int mbase = (wid & 3) * 32;
    int nbase = (wid >> 2) * 32;
    int gq = lane >> 2, tig = lane & 3;

    float acc[2][4][4];
#pragma unroll
    for (int mi = 0; mi < 2; mi++)
#pragma unroll
        for (int nj = 0; nj < 4; nj++)
#pragma unroll
            for (int r = 0; r < 4; r++) acc[mi][nj][r] = 0.f;

    int r0g = m0 + a_r, r1g = m0 + a_r + 64;

    // tile store helper (macro to keep register use predictable)
#define STORE_TILE(BUF, VA0, VA1, VB)                                          \
    do {                                                                       \
        if (passes == 3) {                                                     \
            uint4 h, l;                                                        \
            cvt_hilo(VA0.x, h.x, l.x); cvt_hilo(VA0.y, h.y, l.y);              \
            cvt_hilo(VA0.z, h.z, l.z); cvt_hilo(VA0.w, h.w, l.w);              \
            *(uint4*)&As_hi[BUF][a_r][a_c] = h;  *(uint4*)&As_lo[BUF][a_r][a_c] = l; \
            cvt_hilo(VA1.x, h.x, l.x); cvt_hilo(VA1.y, h.y, l.y);              \
            cvt_hilo(VA1.z, h.z, l.z); cvt_hilo(VA1.w, h.w, l.w);              \
            *(uint4*)&As_hi[BUF][a_r + 64][a_c] = h;  *(uint4*)&As_lo[BUF][a_r + 64][a_c] = l; \
            cvt_hilo(VB.x, h.x, l.x); cvt_hilo(VB.y, h.y, l.y);                \
            cvt_hilo(VB.z, h.z, l.z); cvt_hilo(VB.w, h.w, l.w);                \
            *(uint4*)&Bs_hi[BUF][b_r][b_c] = h;  *(uint4*)&Bs_lo[BUF][b_r][b_c] = l; \
        } else {                                                               \
            uint4 h;                                                           \
            h.x = cvt_hi(VA0.x); h.y = cvt_hi(VA0.y);                          \
            h.z = cvt_hi(VA0.z); h.w = cvt_hi(VA0.w);                          \
            *(uint4*)&As_hi[BUF][a_r][a_c] = h;                                \
            h.x = cvt_hi(VA1.x); h.y = cvt_hi(VA1.y);                          \
            h.z = cvt_hi(VA1.z); h.w = cvt_hi(VA1.w);                          \
            *(uint4*)&As_hi[BUF][a_r + 64][a_c] = h;                           \
            h.x = cvt_hi(VB.x); h.y = cvt_hi(VB.y);                            \
            h.z = cvt_hi(VB.z); h.w = cvt_hi(VB.w);                            \
            *(uint4*)&Bs_hi[BUF][b_r][b_c] = h;                                \
        }                                                                      \
    } while (0)

    // prologue: tile 0 -> smem buf 0
    {
        float4 va0 = (r0g < M) ? a_transform(*(const float4*)(A + (size_t)r0g * K + a_c), a_c, a_mode)
                               : make_float4(0,0,0,0);
        float4 va1 = (r1g < M) ? a_transform(*(const float4*)(A + (size_t)r1g * K + a_c), a_c, a_mode)
                               : make_float4(0,0,0,0);
        float4 vb  = *(const float4*)(B + (size_t)b_r * ldb + n0 + b_c);
        STORE_TILE(0, va0, va1, vb);
    }
    __syncthreads();

    int KT = K / BK;
    for (int kt = 0; kt < KT; kt++) {
        int cur = kt & 1, nxt = cur ^ 1;

        float4 va0, va1, vb;
        bool have_next = (kt + 1 < KT);
        if (have_next) {
            int k0g = (kt + 1) * BK;
            va0 = (r0g < M) ? a_transform(*(const float4*)(A + (size_t)r0g * K + k0g + a_c), k0g + a_c, a_mode)
                            : make_float4(0,0,0,0);
            va1 = (r1g < M) ? a_transform(*(const float4*)(A + (size_t)r1g * K + k0g + a_c), k0g + a_c, a_mode)
                            : make_float4(0,0,0,0);
            vb  = *(const float4*)(B + (size_t)(k0g + b_r) * ldb + n0 + b_c);
        }

        // compute on buffer `cur`
#pragma unroll
        for (int ks = 0; ks < 2; ks++) {
            int k0 = ks * 8;
            uint32_t ah[2][4], al[2][4];
#pragma unroll
            for (int mi = 0; mi < 2; mi++) {
                int r = mbase + mi * 16 + gq;
                ah[mi][0] = As_hi[cur][r][k0 + tig];
                ah[mi][1] = As_hi[cur][r + 8][k0 + tig];
                ah[mi][2] = As_hi[cur][r][k0 + tig + 4];
                ah[mi][3] = As_hi[cur][r + 8][k0 + tig + 4];
                if (passes == 3) {
                    al[mi][0] = As_lo[cur][r][k0 + tig];
                    al[mi][1] = As_lo[cur][r + 8][k0 + tig];
                    al[mi][2] = As_lo[cur][r][k0 + tig + 4];
                    al[mi][3] = As_lo[cur][r + 8][k0 + tig + 4];
                }
            }
#pragma unroll
            for (int nj = 0; nj < 4; nj++) {
                int cn = nbase + nj * 8 + gq;
                uint32_t bh0 = Bs_hi[cur][k0 + tig][cn],     bh1 = Bs_hi[cur][k0 + tig + 4][cn];
#pragma unroll
                for (int mi = 0; mi < 2; mi++)
                    MMA_TF32(acc[mi][nj], ah[mi][0], ah[mi][1], ah[mi][2], ah[mi][3], bh0, bh1);
                if (passes == 3) {
                    uint32_t bl0 = Bs_lo[cur][k0 + tig][cn], bl1 = Bs_lo[cur][k0 + tig + 4][cn];
#pragma unroll
                    for (int mi = 0; mi < 2; mi++) {
                        MMA_TF32(acc[mi][nj], ah[mi][0], ah[mi][1], ah[mi][2], ah[mi][3], bl0, bl1);
                        MMA_TF32(acc[mi][nj], al[mi][0], al[mi][1], al[mi][2], al[mi][3], bh0, bh1);
                    }
                }
            }
        }

        if (have_next) {
            STORE_TILE(nxt, va0, va1, vb);
            __syncthreads();
        }
    }
#undef STORE_TILE

    float* Cagg = agg_sel ? buf_sel(agg_sel) : nullptr;
#pragma unroll
    for (int mi = 0; mi < 2; mi++) {
#pragma unroll
        for (int nj = 0; nj < 4; nj++) {
            int row0 = m0 + mbase + mi * 16 + gq;
            int col  = n0 + nbase + nj * 8 + tig * 2;
#pragma unroll
            for (int h = 0; h < 2; h++) {
                int r = row0 + h * 8;
                if (r >= M) continue;
                float vx = acc[mi][nj][h * 2], vy = acc[mi][nj][h * 2 + 1];
                float2 v = make_float2(vx, vy);
                *(float2*)(C + (size_t)r * ldc + col) = v;
                if (agg_sel) {
                    float dv = g_dinv[r]; dv *= dv;
                    float2 w;
                    w.x = fmaf(vx, dv, bias[col]);
                    w.y = fmaf(vy, dv, bias[col + 1]);
                    *(float2*)(Cagg + (size_t)r * HD + col) = w;
                }
            }
        }
    }
}

// ---------------- edge MLP: out[e] = sigmoid( relu(AB_A[s]+AB_B[d]+bm1) . Wm2 + bm2 ) ----------------
__global__ __launch_bounds__(256) void k_edge_mlp(const int* __restrict__ src,
                                                  const int* __restrict__ dst,
                                                  const float* __restrict__ bm1,
                                                  const float* __restrict__ Wm2,
                                                  const float* __restrict__ bm2,
                                                  float* __restrict__ out, int e) {
    __shared__ __align__(16) float w[HD];
    __shared__ __align__(16) float b[HD];
    int tid = threadIdx.x;
    w[tid] = Wm2[tid];
    b[tid] = bm1[tid];
    __syncthreads();
    int ei = blockIdx.x * 8 + (tid >> 5);
    if (ei >= e) return;
    int lane = tid & 31;
    int s = src[ei], d = dst[ei];
    const float* pa = g_AB + (size_t)s * 512;
    const float* pb = g_AB + (size_t)d * 512 + HD;
    float acc = 0.f;
#pragma unroll
    for (int it = 0; it < 2; it++) {
        int j = (it * 32 + lane) << 2;
        float4 va = *(const float4*)(pa + j);
        float4 vb = *(const float4*)(pb + j);
        float4 vbi = *(const float4*)(b + j);
        float4 vw = *(const float4*)(w + j);
        acc += fmaxf(va.x + vb.x + vbi.x, 0.f) * vw.x;
        acc += fmaxf(va.y + vb.y + vbi.y, 0.f) * vw.y;
        acc += fmaxf(va.z + vb.z + vbi.z, 0.f) * vw.z;
        acc += fmaxf(va.w + vb.w + vbi.w, 0.f) * vw.w;
    }
#pragma unroll
    for (int o = 16; o; o >>= 1) acc += __shfl_xor_sync(0xffffffffu, acc, o);
    if (lane == 0) {
        float z = acc + bm2[0];
        out[ei] = 1.0f / (1.0f + expf(-z));
    }
}

// ---------------- launch ----------------
extern "C" void kernel_launch(void* const* d_in, const int* in_sizes, int n_in,
                              void* d_out, int out_size) {
    const float* x    = (const float*)d_in[0];
    const int*   ei   = (const int*)d_in[1];     // edge_index delivered as int32
    const float* W1   = (const float*)d_in[2];
    const float* b1   = (const float*)d_in[3];
    const float* gamma= (const float*)d_in[4];
    const float* beta = (const float*)d_in[5];
    const float* W2   = (const float*)d_in[6];
    const float* b2   = (const float*)d_in[7];
    const float* Wm1  = (const float*)d_in[8];
    const float* bm1  = (const float*)d_in[9];
    const float* Wm2  = (const float*)d_in[10];
    const float* bm2  = (const float*)d_in[11];
    float* out = (float*)d_out;

    const int n = in_sizes[0] / 128;      // 50000
    const int e = in_sizes[1] / 2;        // 400000
    const int* src = ei;
    const int* dst = ei + e;

    // 1. degrees / norm
    k_init<<<(n + 255) / 256, 256>>>(n);
    k_deg_edges<<<(e + 255) / 256, 256>>>(dst, e);
    k_dinv<<<(n + 255) / 256, 256>>>(n);

    dim3 g1(HD / 64, (n + 127) / 128);    // 4 x 391

    // 2. gcn1: buf1 = x@W1 (3xTF32), fused agg-init -> buf2 ; edge agg buf1 -> buf2
    k_gemm<<<g1, 256>>>(x, 0, 0, 3, W1, 1, 0, HD, 2, b1, n, 128, HD);
    k_edge_agg<<<(e * 64 + 255) / 256, 256>>>(src, dst, 1, 2, e);

    // 3. batchnorm stats (apply is fused into the next GEMM's A-load)
    k_bn_stats<<<512, 256>>>(n);
    k_bn_finalize<<<1, 256>>>(gamma, beta, n);

    // 4. gcn2: buf1 = bn_relu(buf2)@W2 (3xTF32), fused agg-init -> buf3 ; edge agg buf1 -> buf3
    k_gemm<<<g1, 256>>>(nullptr, 2, 2, 3, W2, 1, 0, HD, 4, b2, n, HD, HD);
    k_edge_agg<<<(e * 64 + 255) / 256, 256>>>(src, dst, 1, 4, e);

    // 5. hoisted MLP layer 1 (relu fused into A-load, single-pass TF32 — last layer, error budget OK):
    k_gemm<<<g1, 256>>>(nullptr, 4, 1, 1, Wm1,            3, 0,  512, 0, nullptr, n, HD, HD);
    k_gemm<<<g1, 256>>>(nullptr, 4, 1, 1, Wm1 + 256 * HD, 3, HD, 512, 0, nullptr, n, HD, HD);

    // 6. per-edge epilogue
    k_edge_mlp<<<(e + 7) / 8, 256>>>(src, dst, bm1, Wm2, bm2, out, e);
}

// round 15
// speedup vs baseline: 1.1678x; 1.0563x over previous
#include <cuda_runtime.h>
#include <cuda_bf16.h>
#include <math.h>
#include <stdint.h>

#define NN 50000
#define EE 400000
#define HD 256
#define EPS 1e-5f

// ---------------- scratch (device globals, referenced BY NAME in device code) ----------------
__device__ __align__(16) float g_dinv[NN];                  // deg -> rsqrt(deg)
__device__ __align__(16) float g_buf1[(size_t)NN * HD];     // xw1 , then t (=h1@W2)
__device__ __align__(16) float g_buf2[(size_t)NN * HD];     // agg1
__device__ __align__(16) float g_buf3[(size_t)NN * HD];     // agg2 (h2 = relu(buf3) on the fly)
__device__ __align__(16) __nv_bfloat16 g_AB[(size_t)NN * 512]; // [A | B] per node, bf16
__device__ __align__(16) float g_stats[512];                // per-channel sum, sumsq
__device__ __align__(16) float g_scale[HD];
__device__ __align__(16) float g_shift[HD];

__device__ __forceinline__ float* buf_sel(int s) {          // 1->buf1, 2->buf2, 4->buf3
    return s == 1 ? g_buf1 : (s == 2 ? g_buf2 : g_buf3);
}

// ---------------- small kernels ----------------
__global__ void k_init(int n) {
    int i = blockIdx.x * blockDim.x + threadIdx.x;
    if (i < n) g_dinv[i] = 1.0f;         // self loop contributes 1 to degree
    if (i < 512) g_stats[i] = 0.0f;
}

__global__ void k_deg_edges(const int* __restrict__ dst, int e) {
    int i = blockIdx.x * blockDim.x + threadIdx.x;
    if (i < e) atomicAdd(&g_dinv[dst[i]], 1.0f);
}

__global__ void k_dinv(int n) {
    int i = blockIdx.x * blockDim.x + threadIdx.x;
    if (i < n) g_dinv[i] = rsqrtf(g_dinv[i]);
}

// per edge: agg[dst,:] += xw[src,:] * dinv[src]*dinv[dst]   (64 threads/edge, RED.128)
__global__ void k_edge_agg(const int* __restrict__ src, const int* __restrict__ dst,
                           int xw_sel, int agg_sel, int e) {
    int t = blockIdx.x * blockDim.x + threadIdx.x;
    int ei = t >> 6;
    if (ei >= e) return;
    const float* xw = buf_sel(xw_sel);
    float* agg      = buf_sel(agg_sel);
    int q = (t & 63) << 2;
    int s = src[ei], d = dst[ei];
    float c = g_dinv[s] * g_dinv[d];
    float4 v = *(const float4*)(xw + (size_t)s * HD + q);
    v.x *= c; v.y *= c; v.z *= c; v.w *= c;
#if __CUDA_ARCH__ >= 900
    atomicAdd((float4*)(agg + (size_t)d * HD + q), v);
#else
    float* p = agg + (size_t)d * HD + q;
    atomicAdd(p + 0, v.x); atomicAdd(p + 1, v.y);
    atomicAdd(p + 2, v.z); atomicAdd(p + 3, v.w);
#endif
}

__global__ void k_bn_stats(int n) {                          // reads buf2
    int c = threadIdx.x;                                     // 256 channels
    float s = 0.f, s2 = 0.f;
    for (int r = blockIdx.x; r < n; r += gridDim.x) {
        float v = g_buf2[(size_t)r * HD + c];
        s += v; s2 += v * v;
    }
    atomicAdd(&g_stats[c], s);
    atomicAdd(&g_stats[HD + c], s2);
}

__global__ void k_bn_finalize(const float* __restrict__ gamma, const float* __restrict__ beta, int n) {
    int c = threadIdx.x;
    float inv_n = 1.0f / (float)n;
    float mu = g_stats[c] * inv_n;
    float var = g_stats[HD + c] * inv_n - mu * mu;
    float sc = gamma[c] * rsqrtf(var + EPS);
    g_scale[c] = sc;
    g_shift[c] = beta[c] - mu * sc;
}

// ---------------- TF32 tensor-core GEMM, double-buffered (passes = 3: full 3xTF32; 1: fast) ----------------
__device__ __forceinline__ void cvt_hilo(float x, uint32_t& hi, uint32_t& lo) {
    uint32_t h;
    asm("cvt.rna.tf32.f32 %0, %1;" : "=r"(h) : "f"(x));
    float l = x - __uint_as_float(h);
    uint32_t lw;
    asm("cvt.rna.tf32.f32 %0, %1;" : "=r"(lw) : "f"(l));
    hi = h; lo = lw;
}

__device__ __forceinline__ uint32_t cvt_hi(float x) {
    uint32_t h;
    asm("cvt.rna.tf32.f32 %0, %1;" : "=r"(h) : "f"(x));
    return h;
}

#define MMA_TF32(c, a0, a1, a2, a3, b0, b1)                                   \
    asm volatile("mma.sync.aligned.m16n8k8.row.col.f32.tf32.tf32.f32 "        \
                 "{%0,%1,%2,%3}, {%4,%5,%6,%7}, {%8,%9}, {%0,%1,%2,%3};"      \
                 : "+f"(c[0]), "+f"(c[1]), "+f"(c[2]), "+f"(c[3])             \
                 : "r"(a0), "r"(a1), "r"(a2), "r"(a3), "r"(b0), "r"(b1))

// A-load transform: 0 = none, 1 = relu, 2 = bn(scale,shift)+relu (per-column = k index)
__device__ __forceinline__ float4 a_transform(float4 v, int kcol, int a_mode) {
    if (a_mode == 1) {
        v.x = fmaxf(v.x, 0.f); v.y = fmaxf(v.y, 0.f);
        v.z = fmaxf(v.z, 0.f); v.w = fmaxf(v.w, 0.f);
    } else if (a_mode == 2) {
        v.x = fmaxf(fmaf(v.x, g_scale[kcol + 0], g_shift[kcol + 0]), 0.f);
        v.y = fmaxf(fmaf(v.y, g_scale[kcol + 1], g_shift[kcol + 1]), 0.f);
        v.z = fmaxf(fmaf(v.z, g_scale[kcol + 2], g_shift[kcol + 2]), 0.f);
        v.w = fmaxf(fmaf(v.w, g_scale[kcol + 3], g_shift[kcol + 3]), 0.f);
    }
    return v;
}

// C = f(A)[M,K] @ B[K,ldb].  passes=3: fp32-accurate 3xTF32; passes=1: plain TF32.
// c_sel 1/2/4: fp32 buf.  c_sel 3: bf16 store into g_AB (ldc=512, offset c_off).
__global__ __launch_bounds__(256, 2) void k_gemm(const float* __restrict__ Aext, int a_sel, int a_mode,
                                                 int passes,
                                                 const float* __restrict__ B,
                                                 int c_sel, int c_off, int ldc,
                                                 int agg_sel, const float* __restrict__ bias,
                                                 int M, int K, int ldb) {
    const int BM = 128, BN = 64, BK = 16;
    const int SA = BK + 4;   // 20
    const int SB = BN + 8;   // 72
    __shared__ __align__(16) uint32_t As_hi[2][BM][SA], As_lo[2][BM][SA];
    __shared__ __align__(16) uint32_t Bs_hi[2][BK][SB], Bs_lo[2][BK][SB];

    const float* A = (a_sel == 0) ? Aext : buf_sel(a_sel);
    float* C = (c_sel == 3) ? nullptr : (buf_sel(c_sel) + c_off);

    int tid = threadIdx.x;
    int m0 = blockIdx.y * BM;
    int n0 = blockIdx.x * BN;

    int a_r = tid >> 2;              // 0..63 (rows a_r and a_r+64)
    int a_c = (tid & 3) << 2;        // 0,4,8,12 (k group of 4)
    int b_r = tid >> 4;              // 0..15 (k)
    int b_c = (tid & 15) << 2;       // 0..60 (n group of 4)

    int wid = tid >> 5, lane = tid & 31;
    int mbase = (wid & 3) * 32;
    int nbase = (wid >> 2) * 32;
    int gq = lane >> 2, tig = lane & 3;

    float acc[2][4][4];
#pragma unroll
    for (int mi = 0; mi < 2; mi++)
#pragma unroll
        for (int nj = 0; nj < 4; nj++)
#pragma unroll
            for (int r = 0; r < 4; r++) acc[mi][nj][r] = 0.f;

    int r0g = m0 + a_r, r1g = m0 + a_r + 64;

#define STORE_TILE(BUF, VA0, VA1, VB)                                          \
    do {                                                                       \
        if (passes == 3) {                                                     \
            uint4 h, l;                                                        \
            cvt_hilo(VA0.x, h.x, l.x); cvt_hilo(VA0.y, h.y, l.y);              \
            cvt_hilo(VA0.z, h.z, l.z); cvt_hilo(VA0.w, h.w, l.w);              \
            *(uint4*)&As_hi[BUF][a_r][a_c] = h;  *(uint4*)&As_lo[BUF][a_r][a_c] = l; \
            cvt_hilo(VA1.x, h.x, l.x); cvt_hilo(VA1.y, h.y, l.y);              \
            cvt_hilo(VA1.z, h.z, l.z); cvt_hilo(VA1.w, h.w, l.w);              \
            *(uint4*)&As_hi[BUF][a_r + 64][a_c] = h;  *(uint4*)&As_lo[BUF][a_r + 64][a_c] = l; \
            cvt_hilo(VB.x, h.x, l.x); cvt_hilo(VB.y, h.y, l.y);                \
            cvt_hilo(VB.z, h.z, l.z); cvt_hilo(VB.w, h.w, l.w);                \
            *(uint4*)&Bs_hi[BUF][b_r][b_c] = h;  *(uint4*)&Bs_lo[BUF][b_r][b_c] = l; \
        } else {                                                               \
            uint4 h;                                                           \
            h.x = cvt_hi(VA0.x); h.y = cvt_hi(VA0.y);                          \
            h.z = cvt_hi(VA0.z); h.w = cvt_hi(VA0.w);                          \
            *(uint4*)&As_hi[BUF][a_r][a_c] = h;                                \
            h.x = cvt_hi(VA1.x); h.y = cvt_hi(VA1.y);                          \
            h.z = cvt_hi(VA1.z); h.w = cvt_hi(VA1.w);                          \
            *(uint4*)&As_hi[BUF][a_r + 64][a_c] = h;                           \
            h.x = cvt_hi(VB.x); h.y = cvt_hi(VB.y);                            \
            h.z = cvt_hi(VB.z); h.w = cvt_hi(VB.w);                            \
            *(uint4*)&Bs_hi[BUF][b_r][b_c] = h;                                \
        }                                                                      \
    } while (0)

    // prologue: tile 0 -> smem buf 0
    {
        float4 va0 = (r0g < M) ? a_transform(*(const float4*)(A + (size_t)r0g * K + a_c), a_c, a_mode)
                               : make_float4(0,0,0,0);
        float4 va1 = (r1g < M) ? a_transform(*(const float4*)(A + (size_t)r1g * K + a_c), a_c, a_mode)
                               : make_float4(0,0,0,0);
        float4 vb  = *(const float4*)(B + (size_t)b_r * ldb + n0 + b_c);
        STORE_TILE(0, va0, va1, vb);
    }
    __syncthreads();

    int KT = K / BK;
    for (int kt = 0; kt < KT; kt++) {
        int cur = kt & 1, nxt = cur ^ 1;

        float4 va0, va1, vb;
        bool have_next = (kt + 1 < KT);
        if (have_next) {
            int k0g = (kt + 1) * BK;
            va0 = (r0g < M) ? a_transform(*(const float4*)(A + (size_t)r0g * K + k0g + a_c), k0g + a_c, a_mode)
                            : make_float4(0,0,0,0);
            va1 = (r1g < M) ? a_transform(*(const float4*)(A + (size_t)r1g * K + k0g + a_c), k0g + a_c, a_mode)
                            : make_float4(0,0,0,0);
            vb  = *(const float4*)(B + (size_t)(k0g + b_r) * ldb + n0 + b_c);
        }

#pragma unroll
        for (int ks = 0; ks < 2; ks++) {
            int k0 = ks * 8;
            uint32_t ah[2][4], al[2][4];
#pragma unroll
            for (int mi = 0; mi < 2; mi++) {
                int r = mbase + mi * 16 + gq;
                ah[mi][0] = As_hi[cur][r][k0 + tig];
                ah[mi][1] = As_hi[cur][r + 8][k0 + tig];
                ah[mi][2] = As_hi[cur][r][k0 + tig + 4];
                ah[mi][3] = As_hi[cur][r + 8][k0 + tig + 4];
                if (passes == 3) {
                    al[mi][0] = As_lo[cur][r][k0 + tig];
                    al[mi][1] = As_lo[cur][r + 8][k0 + tig];
                    al[mi][2] = As_lo[cur][r][k0 + tig + 4];
                    al[mi][3] = As_lo[cur][r + 8][k0 + tig + 4];
                }
            }
#pragma unroll
            for (int nj = 0; nj < 4; nj++) {
                int cn = nbase + nj * 8 + gq;
                uint32_t bh0 = Bs_hi[cur][k0 + tig][cn],     bh1 = Bs_hi[cur][k0 + tig + 4][cn];
#pragma unroll
                for (int mi = 0; mi < 2; mi++)
                    MMA_TF32(acc[mi][nj], ah[mi][0], ah[mi][1], ah[mi][2], ah[mi][3], bh0, bh1);
                if (passes == 3) {
                    uint32_t bl0 = Bs_lo[cur][k0 + tig][cn], bl1 = Bs_lo[cur][k0 + tig + 4][cn];
#pragma unroll
                    for (int mi = 0; mi < 2; mi++) {
                        MMA_TF32(acc[mi][nj], ah[mi][0], ah[mi][1], ah[mi][2], ah[mi][3], bl0, bl1);
                        MMA_TF32(acc[mi][nj], al[mi][0], al[mi][1], al[mi][2], al[mi][3], bh0, bh1);
                    }
                }
            }
        }

        if (have_next) {
            STORE_TILE(nxt, va0, va1, vb);
            __syncthreads();
        }
    }
#undef STORE_TILE

    float* Cagg = agg_sel ? buf_sel(agg_sel) : nullptr;
#pragma unroll
    for (int mi = 0; mi < 2; mi++) {
#pragma unroll
        for (int nj = 0; nj < 4; nj++) {
            int row0 = m0 + mbase + mi * 16 + gq;
            int col  = n0 + nbase + nj * 8 + tig * 2;
#pragma unroll
            for (int h = 0; h < 2; h++) {
                int r = row0 + h * 8;
                if (r >= M) continue;
                float vx = acc[mi][nj][h * 2], vy = acc[mi][nj][h * 2 + 1];
                if (c_sel == 3) {
                    __nv_bfloat162 hv = __float22bfloat162_rn(make_float2(vx, vy));
                    *(__nv_bfloat162*)(g_AB + (size_t)r * 512 + c_off + col) = hv;
                } else {
                    *(float2*)(C + (size_t)r * ldc + col) = make_float2(vx, vy);
                }
                if (agg_sel) {
                    float dv = g_dinv[r]; dv *= dv;
                    float2 w;
                    w.x = fmaf(vx, dv, bias[col]);
                    w.y = fmaf(vy, dv, bias[col + 1]);
                    *(float2*)(Cagg + (size_t)r * HD + col) = w;
                }
            }
        }
    }
}

// ---------------- edge MLP: out[e] = sigmoid( relu(AB_A[s]+AB_B[d]+bm1) . Wm2 + bm2 ) ----------------
__device__ __forceinline__ float4 ldbf4(const __nv_bfloat16* p) {
    uint2 u = *(const uint2*)p;
    __nv_bfloat162 p0 = *reinterpret_cast<__nv_bfloat162*>(&u.x);
    __nv_bfloat162 p1 = *reinterpret_cast<__nv_bfloat162*>(&u.y);
    float2 f0 = __bfloat1622float2(p0), f1 = __bfloat1622float2(p1);
    return make_float4(f0.x, f0.y, f1.x, f1.y);
}

__global__ __launch_bounds__(256) void k_edge_mlp(const int* __restrict__ src,
                                                  const int* __restrict__ dst,
                                                  const float* __restrict__ bm1,
                                                  const float* __restrict__ Wm2,
                                                  const float* __restrict__ bm2,
                                                  float* __restrict__ out, int e) {
    __shared__ __align__(16) float w[HD];
    __shared__ __align__(16) float b[HD];
    int tid = threadIdx.x;
    w[tid] = Wm2[tid];
    b[tid] = bm1[tid];
    __syncthreads();
    int ei = blockIdx.x * 8 + (tid >> 5);
    if (ei >= e) return;
    int lane = tid & 31;
    int s = src[ei], d = dst[ei];
    const __nv_bfloat16* pa = g_AB + (size_t)s * 512;
    const __nv_bfloat16* pb = g_AB + (size_t)d * 512 + HD;
    float acc = 0.f;
#pragma unroll
    for (int it = 0; it < 2; it++) {
        int j = (it * 32 + lane) << 2;
        float4 va = ldbf4(pa + j);
        float4 vb = ldbf4(pb + j);
        float4 vbi = *(const float4*)(b + j);
        float4 vw = *(const float4*)(w + j);
        acc += fmaxf(va.x + vb.x + vbi.x, 0.f) * vw.x;
        acc += fmaxf(va.y + vb.y + vbi.y, 0.f) * vw.y;
        acc += fmaxf(va.z + vb.z + vbi.z, 0.f) * vw.z;
        acc += fmaxf(va.w + vb.w + vbi.w, 0.f) * vw.w;
    }
#pragma unroll
    for (int o = 16; o; o >>= 1) acc += __shfl_xor_sync(0xffffffffu, acc, o);
    if (lane == 0) {
        float z = acc + bm2[0];
        out[ei] = 1.0f / (1.0f + expf(-z));
    }
}

// ---------------- launch ----------------
extern "C" void kernel_launch(void* const* d_in, const int* in_sizes, int n_in,
                              void* d_out, int out_size) {
    const float* x    = (const float*)d_in[0];
    const int*   ei   = (const int*)d_in[1];     // edge_index delivered as int32
    const float* W1   = (const float*)d_in[2];
    const float* b1   = (const float*)d_in[3];
    const float* gamma= (const float*)d_in[4];
    const float* beta = (const float*)d_in[5];
    const float* W2   = (const float*)d_in[6];
    const float* b2   = (const float*)d_in[7];
    const float* Wm1  = (const float*)d_in[8];
    const float* bm1  = (const float*)d_in[9];
    const float* Wm2  = (const float*)d_in[10];
    const float* bm2  = (const float*)d_in[11];
    float* out = (float*)d_out;

    const int n = in_sizes[0] / 128;      // 50000
    const int e = in_sizes[1] / 2;        // 400000
    const int* src = ei;
    const int* dst = ei + e;

    // 1. degrees / norm
    k_init<<<(n + 255) / 256, 256>>>(n);
    k_deg_edges<<<(e + 255) / 256, 256>>>(dst, e);
    k_dinv<<<(n + 255) / 256, 256>>>(n);

    dim3 g1(HD / 64, (n + 127) / 128);    // 4 x 391

    // 2. gcn1: buf1 = x@W1 (3xTF32), fused agg-init -> buf2 ; edge agg buf1 -> buf2
    k_gemm<<<g1, 256>>>(x, 0, 0, 3, W1, 1, 0, HD, 2, b1, n, 128, HD);
    k_edge_agg<<<(e * 64 + 255) / 256, 256>>>(src, dst, 1, 2, e);

    // 3. batchnorm stats (apply is fused into the next GEMM's A-load)
    k_bn_stats<<<512, 256>>>(n);
    k_bn_finalize<<<1, 256>>>(gamma, beta, n);

    // 4. gcn2: buf1 = bn_relu(buf2)@W2 (3xTF32), fused agg-init -> buf3 ; edge agg buf1 -> buf3
    k_gemm<<<g1, 256>>>(nullptr, 2, 2, 3, W2, 1, 0, HD, 4, b2, n, HD, HD);
    k_edge_agg<<<(e * 64 + 255) / 256, 256>>>(src, dst, 1, 4, e);

    // 5. hoisted MLP layer 1 (relu fused into A-load, single-pass TF32, bf16 output into g_AB):
    k_gemm<<<g1, 256>>>(nullptr, 4, 1, 1, Wm1,            3, 0,  512, 0, nullptr, n, HD, HD);
    k_gemm<<<g1, 256>>>(nullptr, 4, 1, 1, Wm1 + 256 * HD, 3, HD, 512, 0, nullptr, n, HD, HD);

    // 6. per-edge epilogue (bf16 gathers)
    k_edge_mlp<<<(e + 7) / 8, 256>>>(src, dst, bm1, Wm2, bm2, out, e);
}

// round 16
// speedup vs baseline: 1.2071x; 1.0337x over previous
#include <cuda_runtime.h>
#include <cuda_bf16.h>
#include <math.h>
#include <stdint.h>

#define NN 50000
#define EE 400000
#define HD 256
#define EPS 1e-5f

// ---------------- scratch (device globals, referenced BY NAME in device code) ----------------
__device__ __align__(16) float g_dinv[NN];                  // deg -> rsqrt(deg)
__device__ __align__(16) float g_buf2[(size_t)NN * HD];     // agg1
__device__ __align__(16) float g_buf3[(size_t)NN * HD];     // agg2 (h2 = relu(buf3) on the fly)
__device__ __align__(16) __nv_bfloat16 g_xwb[(size_t)NN * HD];  // bf16 xw (gather source for edge_agg)
__device__ __align__(16) __nv_bfloat16 g_AB[(size_t)NN * 512];  // [A | B] per node, bf16
__device__ __align__(16) float g_stats[512];                // per-channel sum, sumsq
__device__ __align__(16) float g_scale[HD];
__device__ __align__(16) float g_shift[HD];

__device__ __forceinline__ float* buf_sel(int s) {          // 2->buf2, 4->buf3
    return s == 2 ? g_buf2 : g_buf3;
}

// ---------------- small kernels ----------------
__global__ void k_init(int n) {
    int i = blockIdx.x * blockDim.x + threadIdx.x;
    if (i < n) g_dinv[i] = 1.0f;         // self loop contributes 1 to degree
    if (i < 512) g_stats[i] = 0.0f;
}

__global__ void k_deg_edges(const int* __restrict__ dst, int e) {
    int i = blockIdx.x * blockDim.x + threadIdx.x;
    if (i < e) atomicAdd(&g_dinv[dst[i]], 1.0f);
}

__global__ void k_dinv(int n) {
    int i = blockIdx.x * blockDim.x + threadIdx.x;
    if (i < n) g_dinv[i] = rsqrtf(g_dinv[i]);
}

__device__ __forceinline__ float4 ldbf4(const __nv_bfloat16* p) {
    uint2 u = *(const uint2*)p;
    __nv_bfloat162 p0 = *reinterpret_cast<__nv_bfloat162*>(&u.x);
    __nv_bfloat162 p1 = *reinterpret_cast<__nv_bfloat162*>(&u.y);
    float2 f0 = __bfloat1622float2(p0), f1 = __bfloat1622float2(p1);
    return make_float4(f0.x, f0.y, f1.x, f1.y);
}

// per edge: agg[dst,:] += bf16_xw[src,:] * dinv[src]*dinv[dst]   (64 threads/edge, RED.128)
__global__ void k_edge_agg(const int* __restrict__ src, const int* __restrict__ dst,
                           int agg_sel, int e) {
    int t = blockIdx.x * blockDim.x + threadIdx.x;
    int ei = t >> 6;
    if (ei >= e) return;
    float* agg = buf_sel(agg_sel);
    int q = (t & 63) << 2;
    int s = src[ei], d = dst[ei];
    float c = g_dinv[s] * g_dinv[d];
    float4 v = ldbf4(g_xwb + (size_t)s * HD + q);
    v.x *= c; v.y *= c; v.z *= c; v.w *= c;
#if __CUDA_ARCH__ >= 900
    atomicAdd((float4*)(agg + (size_t)d * HD + q), v);
#else
    float* p = agg + (size_t)d * HD + q;
    atomicAdd(p + 0, v.x); atomicAdd(p + 1, v.y);
    atomicAdd(p + 2, v.z); atomicAdd(p + 3, v.w);
#endif
}

__global__ void k_bn_stats(int n) {                          // reads buf2
    int c = threadIdx.x;                                     // 256 channels
    float s = 0.f, s2 = 0.f;
    for (int r = blockIdx.x; r < n; r += gridDim.x) {
        float v = g_buf2[(size_t)r * HD + c];
        s += v; s2 += v * v;
    }
    atomicAdd(&g_stats[c], s);
    atomicAdd(&g_stats[HD + c], s2);
}

__global__ void k_bn_finalize(const float* __restrict__ gamma, const float* __restrict__ beta, int n) {
    int c = threadIdx.x;
    float inv_n = 1.0f / (float)n;
    float mu = g_stats[c] * inv_n;
    float var = g_stats[HD + c] * inv_n - mu * mu;
    float sc = gamma[c] * rsqrtf(var + EPS);
    g_scale[c] = sc;
    g_shift[c] = beta[c] - mu * sc;
}

// ---------------- TF32 tensor-core GEMM, double-buffered (passes = 3: full 3xTF32; 1: fast) ----------------
__device__ __forceinline__ void cvt_hilo(float x, uint32_t& hi, uint32_t& lo) {
    uint32_t h;
    asm("cvt.rna.tf32.f32 %0, %1;" : "=r"(h) : "f"(x));
    float l = x - __uint_as_float(h);
    uint32_t lw;
    asm("cvt.rna.tf32.f32 %0, %1;" : "=r"(lw) : "f"(l));
    hi = h; lo = lw;
}

__device__ __forceinline__ uint32_t cvt_hi(float x) {
    uint32_t h;
    asm("cvt.rna.tf32.f32 %0, %1;" : "=r"(h) : "f"(x));
    return h;
}

#define MMA_TF32(c, a0, a1, a2, a3, b0, b1)                                   \
    asm volatile("mma.sync.aligned.m16n8k8.row.col.f32.tf32.tf32.f32 "        \
                 "{%0,%1,%2,%3}, {%4,%5,%6,%7}, {%8,%9}, {%0,%1,%2,%3};"      \
                 : "+f"(c[0]), "+f"(c[1]), "+f"(c[2]), "+f"(c[3])             \
                 : "r"(a0), "r"(a1), "r"(a2), "r"(a3), "r"(b0), "r"(b1))

// A-load transform: 0 = none, 1 = relu, 2 = bn(scale,shift)+relu (per-column = k index)
__device__ __forceinline__ float4 a_transform(float4 v, int kcol, int a_mode) {
    if (a_mode == 1) {
        v.x = fmaxf(v.x, 0.f); v.y = fmaxf(v.y, 0.f);
        v.z = fmaxf(v.z, 0.f); v.w = fmaxf(v.w, 0.f);
    } else if (a_mode == 2) {
        v.x = fmaxf(fmaf(v.x, g_scale[kcol + 0], g_shift[kcol + 0]), 0.f);
        v.y = fmaxf(fmaf(v.y, g_scale[kcol + 1], g_shift[kcol + 1]), 0.f);
        v.z = fmaxf(fmaf(v.z, g_scale[kcol + 2], g_shift[kcol + 2]), 0.f);
        v.w = fmaxf(fmaf(v.w, g_scale[kcol + 3], g_shift[kcol + 3]), 0.f);
    }
    return v;
}

// C = f(A)[M,K] @ B[K,ldb].  passes=3: fp32-accurate 3xTF32; passes=1: plain TF32.
// c_sel: 3 -> bf16 into g_AB (ldc=512, +c_off); 5 -> bf16 into g_xwb (ldc=HD);
//        2/4 -> fp32 buf (unused path kept for generality).
__global__ __launch_bounds__(256, 2) void k_gemm(const float* __restrict__ Aext, int a_sel, int a_mode,
                                                 int passes,
                                                 const float* __restrict__ B,
                                                 int c_sel, int c_off, int ldc,
                                                 int agg_sel, const float* __restrict__ bias,
                                                 int M, int K, int ldb) {
    const int BM = 128, BN = 64, BK = 16;
    const int SA = BK + 4;   // 20
    const int SB = BN + 8;   // 72
    __shared__ __align__(16) uint32_t As_hi[2][BM][SA], As_lo[2][BM][SA];
    __shared__ __align__(16) uint32_t Bs_hi[2][BK][SB], Bs_lo[2][BK][SB];

    const float* A = (a_sel == 0) ? Aext : buf_sel(a_sel);

    int tid = threadIdx.x;
    int m0 = blockIdx.y * BM;
    int n0 = blockIdx.x * BN;

    int a_r = tid >> 2;              // 0..63 (rows a_r and a_r+64)
    int a_c = (tid & 3) << 2;        // 0,4,8,12 (k group of 4)
    int b_r = tid >> 4;              // 0..15 (k)
    int b_c = (tid & 15) << 2;       // 0..60 (n group of 4)

    int wid = tid >> 5, lane = tid & 31;
    int mbase = (wid & 3) * 32;
    int nbase = (wid >> 2) * 32;
    int gq = lane >> 2, tig = lane & 3;

    float acc[2][4][4];
#pragma unroll
    for (int mi = 0; mi < 2; mi++)
#pragma unroll
        for (int nj = 0; nj < 4; nj++)
#pragma unroll
            for (int r = 0; r < 4; r++) acc[mi][nj][r] = 0.f;

    int r0g = m0 + a_r, r1g = m0 + a_r + 64;

#define STORE_TILE(BUF, VA0, VA1, VB)                                          \
    do {                                                                       \
        if (passes == 3) {                                                     \
            uint4 h, l;                                                        \
            cvt_hilo(VA0.x, h.x, l.x); cvt_hilo(VA0.y, h.y, l.y);              \
            cvt_hilo(VA0.z, h.z, l.z); cvt_hilo(VA0.w, h.w, l.w);              \
            *(uint4*)&As_hi[BUF][a_r][a_c] = h;  *(uint4*)&As_lo[BUF][a_r][a_c] = l; \
            cvt_hilo(VA1.x, h.x, l.x); cvt_hilo(VA1.y, h.y, l.y);              \
            cvt_hilo(VA1.z, h.z, l.z); cvt_hilo(VA1.w, h.w, l.w);              \
            *(uint4*)&As_hi[BUF][a_r + 64][a_c] = h;  *(uint4*)&As_lo[BUF][a_r + 64][a_c] = l; \
            cvt_hilo(VB.x, h.x, l.x); cvt_hilo(VB.y, h.y, l.y);                \
            cvt_hilo(VB.z, h.z, l.z); cvt_hilo(VB.w, h.w, l.w);                \
            *(uint4*)&Bs_hi[BUF][b_r][b_c] = h;  *(uint4*)&Bs_lo[BUF][b_r][b_c] = l; \
        } else {                                                               \
            uint4 h;                                                           \
            h.x = cvt_hi(VA0.x); h.y = cvt_hi(VA0.y);                          \
            h.z = cvt_hi(VA0.z); h.w = cvt_hi(VA0.w);                          \
            *(uint4*)&As_hi[BUF][a_r][a_c] = h;                                \
            h.x = cvt_hi(VA1.x); h.y = cvt_hi(VA1.y);                          \
            h.z = cvt_hi(VA1.z); h.w = cvt_hi(VA1.w);                          \
            *(uint4*)&As_hi[BUF][a_r + 64][a_c] = h;                           \
            h.x = cvt_hi(VB.x); h.y = cvt_hi(VB.y);                            \
            h.z = cvt_hi(VB.z); h.w = cvt_hi(VB.w);                            \
            *(uint4*)&Bs_hi[BUF][b_r][b_c] = h;                                \
        }                                                                      \
    } while (0)

    // prologue: tile 0 -> smem buf 0
    {
        float4 va0 = (r0g < M) ? a_transform(*(const float4*)(A + (size_t)r0g * K + a_c), a_c, a_mode)
                               : make_float4(0,0,0,0);
        float4 va1 = (r1g < M) ? a_transform(*(const float4*)(A + (size_t)r1g * K + a_c), a_c, a_mode)
                               : make_float4(0,0,0,0);
        float4 vb  = *(const float4*)(B + (size_t)b_r * ldb + n0 + b_c);
        STORE_TILE(0, va0, va1, vb);
    }
    __syncthreads();

    int KT = K / BK;
    for (int kt = 0; kt < KT; kt++) {
        int cur = kt & 1, nxt = cur ^ 1;

        float4 va0, va1, vb;
        bool have_next = (kt + 1 < KT);
        if (have_next) {
            int k0g = (kt + 1) * BK;
            va0 = (r0g < M) ? a_transform(*(const float4*)(A + (size_t)r0g * K + k0g + a_c), k0g + a_c, a_mode)
                            : make_float4(0,0,0,0);
            va1 = (r1g < M) ? a_transform(*(const float4*)(A + (size_t)r1g * K + k0g + a_c), k0g + a_c, a_mode)
                            : make_float4(0,0,0,0);
            vb  = *(const float4*)(B + (size_t)(k0g + b_r) * ldb + n0 + b_c);
        }

#pragma unroll
        for (int ks = 0; ks < 2; ks++) {
            int k0 = ks * 8;
            uint32_t ah[2][4], al[2][4];
#pragma unroll
            for (int mi = 0; mi < 2; mi++) {
                int r = mbase + mi * 16 + gq;
                ah[mi][0] = As_hi[cur][r][k0 + tig];
                ah[mi][1] = As_hi[cur][r + 8][k0 + tig];
                ah[mi][2] = As_hi[cur][r][k0 + tig + 4];
                ah[mi][3] = As_hi[cur][r + 8][k0 + tig + 4];
                if (passes == 3) {
                    al[mi][0] = As_lo[cur][r][k0 + tig];
                    al[mi][1] = As_lo[cur][r + 8][k0 + tig];
                    al[mi][2] = As_lo[cur][r][k0 + tig + 4];
                    al[mi][3] = As_lo[cur][r + 8][k0 + tig + 4];
                }
            }
#pragma unroll
            for (int nj = 0; nj < 4; nj++) {
                int cn = nbase + nj * 8 + gq;
                uint32_t bh0 = Bs_hi[cur][k0 + tig][cn],     bh1 = Bs_hi[cur][k0 + tig + 4][cn];
#pragma unroll
                for (int mi = 0; mi < 2; mi++)
                    MMA_TF32(acc[mi][nj], ah[mi][0], ah[mi][1], ah[mi][2], ah[mi][3], bh0, bh1);
                if (passes == 3) {
                    uint32_t bl0 = Bs_lo[cur][k0 + tig][cn], bl1 = Bs_lo[cur][k0 + tig + 4][cn];
#pragma unroll
                    for (int mi = 0; mi < 2; mi++) {
                        MMA_TF32(acc[mi][nj], ah[mi][0], ah[mi][1], ah[mi][2], ah[mi][3], bl0, bl1);
                        MMA_TF32(acc[mi][nj], al[mi][0], al[mi][1], al[mi][2], al[mi][3], bh0, bh1);
                    }
                }
            }
        }

        if (have_next) {
            STORE_TILE(nxt, va0, va1, vb);
            __syncthreads();
        }
    }
#undef STORE_TILE

    float* Cagg = agg_sel ? buf_sel(agg_sel) : nullptr;
#pragma unroll
    for (int mi = 0; mi < 2; mi++) {
#pragma unroll
        for (int nj = 0; nj < 4; nj++) {
            int row0 = m0 + mbase + mi * 16 + gq;
            int col  = n0 + nbase + nj * 8 + tig * 2;
#pragma unroll
            for (int h = 0; h < 2; h++) {
                int r = row0 + h * 8;
                if (r >= M) continue;
                float vx = acc[mi][nj][h * 2], vy = acc[mi][nj][h * 2 + 1];
                if (c_sel == 3) {
                    __nv_bfloat162 hv = __float22bfloat162_rn(make_float2(vx, vy));
                    *(__nv_bfloat162*)(g_AB + (size_t)r * 512 + c_off + col) = hv;
                } else if (c_sel == 5) {
                    __nv_bfloat162 hv = __float22bfloat162_rn(make_float2(vx, vy));
                    *(__nv_bfloat162*)(g_xwb + (size_t)r * HD + col) = hv;
                } else {
                    *(float2*)(buf_sel(c_sel) + (size_t)r * ldc + c_off + col) = make_float2(vx, vy);
                }
                if (agg_sel) {
                    float dv = g_dinv[r]; dv *= dv;
                    float2 w;
                    w.x = fmaf(vx, dv, bias[col]);
                    w.y = fmaf(vy, dv, bias[col + 1]);
                    *(float2*)(Cagg + (size_t)r * HD + col) = w;
                }
            }
        }
    }
}

// ---------------- edge MLP: out[e] = sigmoid( relu(AB_A[s]+AB_B[d]+bm1) . Wm2 + bm2 ) ----------------
__global__ __launch_bounds__(256) void k_edge_mlp(const int* __restrict__ src,
                                                  const int* __restrict__ dst,
                                                  const float* __restrict__ bm1,
                                                  const float* __restrict__ Wm2,
                                                  const float* __restrict__ bm2,
                                                  float* __restrict__ out, int e) {
    __shared__ __align__(16) float w[HD];
    __shared__ __align__(16) float b[HD];
    int tid = threadIdx.x;
    w[tid] = Wm2[tid];
    b[tid] = bm1[tid];
    __syncthreads();
    int ei = blockIdx.x * 8 + (tid >> 5);
    if (ei >= e) return;
    int lane = tid & 31;
    int s = src[ei], d = dst[ei];
    const __nv_bfloat16* pa = g_AB + (size_t)s * 512;
    const __nv_bfloat16* pb = g_AB + (size_t)d * 512 + HD;
    float acc = 0.f;
#pragma unroll
    for (int it = 0; it < 2; it++) {
        int j = (it * 32 + lane) << 2;
        float4 va = ldbf4(pa + j);
        float4 vb = ldbf4(pb + j);
        float4 vbi = *(const float4*)(b + j);
        float4 vw = *(const float4*)(w + j);
        acc += fmaxf(va.x + vb.x + vbi.x, 0.f) * vw.x;
        acc += fmaxf(va.y + vb.y + vbi.y, 0.f) * vw.y;
        acc += fmaxf(va.z + vb.z + vbi.z, 0.f) * vw.z;
        acc += fmaxf(va.w + vb.w + vbi.w, 0.f) * vw.w;
    }
#pragma unroll
    for (int o = 16; o; o >>= 1) acc += __shfl_xor_sync(0xffffffffu, acc, o);
    if (lane == 0) {
        float z = acc + bm2[0];
        out[ei] = 1.0f / (1.0f + expf(-z));
    }
}

// ---------------- launch ----------------
extern "C" void kernel_launch(void* const* d_in, const int* in_sizes, int n_in,
                              void* d_out, int out_size) {
    const float* x    = (const float*)d_in[0];
    const int*   ei   = (const int*)d_in[1];     // edge_index delivered as int32
    const float* W1   = (const float*)d_in[2];
    const float* b1   = (const float*)d_in[3];
    const float* gamma= (const float*)d_in[4];
    const float* beta = (const float*)d_in[5];
    const float* W2   = (const float*)d_in[6];
    const float* b2   = (const float*)d_in[7];
    const float* Wm1  = (const float*)d_in[8];
    const float* bm1  = (const float*)d_in[9];
    const float* Wm2  = (const float*)d_in[10];
    const float* bm2  = (const float*)d_in[11];
    float* out = (float*)d_out;

    const int n = in_sizes[0] / 128;      // 50000
    const int e = in_sizes[1] / 2;        // 400000
    const int* src = ei;
    const int* dst = ei + e;

    // 1. degrees / norm
    k_init<<<(n + 255) / 256, 256>>>(n);
    k_deg_edges<<<(e + 255) / 256, 256>>>(dst, e);
    k_dinv<<<(n + 255) / 256, 256>>>(n);

    dim3 g1(HD / 64, (n + 127) / 128);    // 4 x 391

    // 2. gcn1: g_xwb = bf16(x@W1) (3xTF32), fused agg-init -> buf2 ; edge agg g_xwb -> buf2
    k_gemm<<<g1, 256>>>(x, 0, 0, 3, W1, 5, 0, HD, 2, b1, n, 128, HD);
    k_edge_agg<<<(e * 64 + 255) / 256, 256>>>(src, dst, 2, e);

    // 3. batchnorm stats (apply is fused into the next GEMM's A-load)
    k_bn_stats<<<512, 256>>>(n);
    k_bn_finalize<<<1, 256>>>(gamma, beta, n);

    // 4. gcn2: g_xwb = bf16(bn_relu(buf2)@W2) (3xTF32), fused agg-init -> buf3 ; edge agg g_xwb -> buf3
    k_gemm<<<g1, 256>>>(nullptr, 2, 2, 3, W2, 5, 0, HD, 4, b2, n, HD, HD);
    k_edge_agg<<<(e * 64 + 255) / 256, 256>>>(src, dst, 4, e);

    // 5. hoisted MLP layer 1 (relu fused into A-load, single-pass TF32, bf16 output into g_AB):
    k_gemm<<<g1, 256>>>(nullptr, 4, 1, 1, Wm1,            3, 0,  512, 0, nullptr, n, HD, HD);
    k_gemm<<<g1, 256>>>(nullptr, 4, 1, 1, Wm1 + 256 * HD, 3, HD, 512, 0, nullptr, n, HD, HD);

    // 6. per-edge epilogue (bf16 gathers)
    k_edge_mlp<<<(e + 7) / 8, 256>>>(src, dst, bm1, Wm2, bm2, out, e);
}

// round 17
// speedup vs baseline: 1.7422x; 1.4433x over previous
#include <cuda_runtime.h>
#include <cuda_bf16.h>
#include <math.h>
#include <stdint.h>

#define NN 50000
#define EE 400000
#define HD 256
#define EPS 1e-5f

// ---------------- scratch (device globals, referenced BY NAME in device code) ----------------
__device__ __align__(16) float g_dinv[NN];                  // deg -> rsqrt(deg)
__device__ __align__(16) float g_buf2[(size_t)NN * HD];     // agg1
__device__ __align__(16) float g_buf3[(size_t)NN * HD];     // agg2 (h2 = relu(buf3) on the fly)
__device__ __align__(16) __nv_bfloat16 g_xwb[(size_t)NN * HD];  // bf16 xw (gather source for edge_agg)
__device__ __align__(16) __nv_bfloat16 g_AB[(size_t)NN * 512];  // [A | B] per node, bf16
__device__ __align__(16) float g_stats[512];                // per-channel sum, sumsq
__device__ __align__(16) float g_scale[HD];
__device__ __align__(16) float g_shift[HD];

__device__ __forceinline__ float* buf_sel(int s) {          // 2->buf2, 4->buf3
    return s == 2 ? g_buf2 : g_buf3;
}

// ---------------- small kernels ----------------
__global__ void k_init(int n) {
    int i = blockIdx.x * blockDim.x + threadIdx.x;
    if (i < n) g_dinv[i] = 1.0f;         // self loop contributes 1 to degree
    if (i < 512) g_stats[i] = 0.0f;
}

__global__ void k_deg_edges(const int* __restrict__ dst, int e) {
    int i = blockIdx.x * blockDim.x + threadIdx.x;
    if (i < e) atomicAdd(&g_dinv[dst[i]], 1.0f);
}

__global__ void k_dinv(int n) {
    int i = blockIdx.x * blockDim.x + threadIdx.x;
    if (i < n) g_dinv[i] = rsqrtf(g_dinv[i]);
}

__device__ __forceinline__ float4 ldbf4(const __nv_bfloat16* p) {
    uint2 u = *(const uint2*)p;
    __nv_bfloat162 p0 = *reinterpret_cast<__nv_bfloat162*>(&u.x);
    __nv_bfloat162 p1 = *reinterpret_cast<__nv_bfloat162*>(&u.y);
    float2 f0 = __bfloat1622float2(p0), f1 = __bfloat1622float2(p1);
    return make_float4(f0.x, f0.y, f1.x, f1.y);
}

// per edge: agg[dst,:] += bf16_xw[src,:] * dinv[src]*dinv[dst]   (64 threads/edge, RED.128)
__global__ void k_edge_agg(const int* __restrict__ src, const int* __restrict__ dst,
                           int agg_sel, int e) {
    int t = blockIdx.x * blockDim.x + threadIdx.x;
    int ei = t >> 6;
    if (ei >= e) return;
    float* agg = buf_sel(agg_sel);
    int q = (t & 63) << 2;
    int s = src[ei], d = dst[ei];
    float c = g_dinv[s] * g_dinv[d];
    float4 v = ldbf4(g_xwb + (size_t)s * HD + q);
    v.x *= c; v.y *= c; v.z *= c; v.w *= c;
#if __CUDA_ARCH__ >= 900
    atomicAdd((float4*)(agg + (size_t)d * HD + q), v);
#else
    float* p = agg + (size_t)d * HD + q;
    atomicAdd(p + 0, v.x); atomicAdd(p + 1, v.y);
    atomicAdd(p + 2, v.z); atomicAdd(p + 3, v.w);
#endif
}

__global__ void k_bn_stats(int n) {                          // reads buf2
    int c = threadIdx.x;                                     // 256 channels
    float s = 0.f, s2 = 0.f;
    for (int r = blockIdx.x; r < n; r += gridDim.x) {
        float v = g_buf2[(size_t)r * HD + c];
        s += v; s2 += v * v;
    }
    atomicAdd(&g_stats[c], s);
    atomicAdd(&g_stats[HD + c], s2);
}

__global__ void k_bn_finalize(const float* __restrict__ gamma, const float* __restrict__ beta, int n) {
    int c = threadIdx.x;
    float inv_n = 1.0f / (float)n;
    float mu = g_stats[c] * inv_n;
    float var = g_stats[HD + c] * inv_n - mu * mu;
    float sc = gamma[c] * rsqrtf(var + EPS);
    g_scale[c] = sc;
    g_shift[c] = beta[c] - mu * sc;
}

// ---------------- bf16 tensor-core GEMM (m16n8k16), double-buffered ----------------
#define MMA_BF16(c, a0, a1, a2, a3, b0, b1)                                   \
    asm volatile("mma.sync.aligned.m16n8k16.row.col.f32.bf16.bf16.f32 "       \
                 "{%0,%1,%2,%3}, {%4,%5,%6,%7}, {%8,%9}, {%0,%1,%2,%3};"      \
                 : "+f"(c[0]), "+f"(c[1]), "+f"(c[2]), "+f"(c[3])             \
                 : "r"(a0), "r"(a1), "r"(a2), "r"(a3), "r"(b0), "r"(b1))

// A-load transform: 0 = none, 1 = relu, 2 = bn(scale,shift)+relu (per-column = k index)
__device__ __forceinline__ float4 a_transform(float4 v, int kcol, int a_mode) {
    if (a_mode == 1) {
        v.x = fmaxf(v.x, 0.f); v.y = fmaxf(v.y, 0.f);
        v.z = fmaxf(v.z, 0.f); v.w = fmaxf(v.w, 0.f);
    } else if (a_mode == 2) {
        v.x = fmaxf(fmaf(v.x, g_scale[kcol + 0], g_shift[kcol + 0]), 0.f);
        v.y = fmaxf(fmaf(v.y, g_scale[kcol + 1], g_shift[kcol + 1]), 0.f);
        v.z = fmaxf(fmaf(v.z, g_scale[kcol + 2], g_shift[kcol + 2]), 0.f);
        v.w = fmaxf(fmaf(v.w, g_scale[kcol + 3], g_shift[kcol + 3]), 0.f);
    }
    return v;
}

__device__ __forceinline__ uint32_t pbf2(float x, float y) {
    __nv_bfloat162 h = __float22bfloat162_rn(make_float2(x, y));   // x -> low (even k)
    return *reinterpret_cast<uint32_t*>(&h);
}

// C = f(A)[M,K] @ B[K,ldb], bf16 inputs, fp32 accumulate.
// c_sel: 3 -> bf16 into g_AB (+c_off, ld 512); 5 -> bf16 into g_xwb (ld HD);
//        2/4 -> fp32 buf.  agg_sel: Cagg = bias + C*dinv[row]^2.
__global__ __launch_bounds__(256, 3) void k_gemm(const float* __restrict__ Aext, int a_sel, int a_mode,
                                                 const float* __restrict__ B,
                                                 int c_sel, int c_off, int ldc,
                                                 int agg_sel, const float* __restrict__ bias,
                                                 int M, int K, int ldb) {
    const int BM = 128, BN = 64, BK = 16;
    const int SA = 12;   // bf16x2 words per A row (8 + 4 pad): frag banks 12*gq+tig all distinct
    const int SB = 12;   // bf16x2 words per B n-row
    __shared__ __align__(16) uint32_t As[2][BM][SA];
    __shared__ __align__(16) uint32_t Bs[2][BN][SB];

    const float* A = (a_sel == 0) ? Aext : buf_sel(a_sel);

    int tid = threadIdx.x;
    int m0 = blockIdx.y * BM;
    int n0 = blockIdx.x * BN;

    // global->smem mapping
    int a_r = tid >> 2;              // 0..63 (rows a_r and a_r+64)
    int a_c = (tid & 3) << 2;        // 0,4,8,12 (k float group of 4)
    int b_n = tid & 31;              // n within tile (and +32)
    int b_k2 = tid >> 5;             // 0..7 : k-pair index

    // warp tiling: 8 warps = 4 (m) x 2 (n); warp tile 32x32
    int wid = tid >> 5, lane = tid & 31;
    int mbase = (wid & 3) * 32;
    int nbase = (wid >> 2) * 32;
    int gq = lane >> 2, tig = lane & 3;

    float acc[2][4][4];
#pragma unroll
    for (int mi = 0; mi < 2; mi++)
#pragma unroll
        for (int nj = 0; nj < 4; nj++)
#pragma unroll
            for (int r = 0; r < 4; r++) acc[mi][nj][r] = 0.f;

    int r0g = m0 + a_r, r1g = m0 + a_r + 64;

#define LOAD_TILE(K0, VA0, VA1, B0, B1, B2, B3)                                \
    do {                                                                       \
        VA0 = (r0g < M) ? a_transform(*(const float4*)(A + (size_t)r0g * K + (K0) + a_c), (K0) + a_c, a_mode) \
                        : make_float4(0,0,0,0);                                \
        VA1 = (r1g < M) ? a_transform(*(const float4*)(A + (size_t)r1g * K + (K0) + a_c), (K0) + a_c, a_mode) \
                        : make_float4(0,0,0,0);                                \
        const float* bp = B + (size_t)((K0) + 2 * b_k2) * ldb + n0 + b_n;      \
        B0 = bp[0];  B1 = bp[ldb];  B2 = bp[32];  B3 = bp[ldb + 32];           \
    } while (0)

#define STORE_TILE(BUF, VA0, VA1, B0, B1, B2, B3)                              \
    do {                                                                       \
        int c2 = a_c >> 1;                                                     \
        As[BUF][a_r][c2]          = pbf2(VA0.x, VA0.y);                        \
        As[BUF][a_r][c2 + 1]      = pbf2(VA0.z, VA0.w);                        \
        As[BUF][a_r + 64][c2]     = pbf2(VA1.x, VA1.y);                        \
        As[BUF][a_r + 64][c2 + 1] = pbf2(VA1.z, VA1.w);                        \
        Bs[BUF][b_n][b_k2]        = pbf2(B0, B1);                              \
        Bs[BUF][b_n + 32][b_k2]   = pbf2(B2, B3);                              \
    } while (0)

    // prologue: tile 0 -> smem buf 0
    {
        float4 va0, va1; float b0, b1, b2, b3;
        LOAD_TILE(0, va0, va1, b0, b1, b2, b3);
        STORE_TILE(0, va0, va1, b0, b1, b2, b3);
    }
    __syncthreads();

    int KT = K / BK;
    for (int kt = 0; kt < KT; kt++) {
        int cur = kt & 1, nxt = cur ^ 1;

        float4 va0, va1; float bb0, bb1, bb2, bb3;
        bool have_next = (kt + 1 < KT);
        if (have_next) LOAD_TILE((kt + 1) * BK, va0, va1, bb0, bb1, bb2, bb3);

        // compute on buffer `cur`: one m16n8k16 per (mi, nj)
        uint32_t a0[2], a1[2], a2[2], a3[2];
#pragma unroll
        for (int mi = 0; mi < 2; mi++) {
            int r = mbase + mi * 16 + gq;
            a0[mi] = As[cur][r][tig];
            a1[mi] = As[cur][r + 8][tig];
            a2[mi] = As[cur][r][tig + 4];
            a3[mi] = As[cur][r + 8][tig + 4];
        }
#pragma unroll
        for (int nj = 0; nj < 4; nj++) {
            int cn = nbase + nj * 8 + gq;
            uint32_t b0 = Bs[cur][cn][tig];
            uint32_t b1 = Bs[cur][cn][tig + 4];
#pragma unroll
            for (int mi = 0; mi < 2; mi++)
                MMA_BF16(acc[mi][nj], a0[mi], a1[mi], a2[mi], a3[mi], b0, b1);
        }

        if (have_next) {
            STORE_TILE(nxt, va0, va1, bb0, bb1, bb2, bb3);
            __syncthreads();
        }
    }
#undef LOAD_TILE
#undef STORE_TILE

    float* Cagg = agg_sel ? buf_sel(agg_sel) : nullptr;
#pragma unroll
    for (int mi = 0; mi < 2; mi++) {
#pragma unroll
        for (int nj = 0; nj < 4; nj++) {
            int row0 = m0 + mbase + mi * 16 + gq;
            int col  = n0 + nbase + nj * 8 + tig * 2;
#pragma unroll
            for (int h = 0; h < 2; h++) {
                int r = row0 + h * 8;
                if (r >= M) continue;
                float vx = acc[mi][nj][h * 2], vy = acc[mi][nj][h * 2 + 1];
                if (c_sel == 3) {
                    __nv_bfloat162 hv = __float22bfloat162_rn(make_float2(vx, vy));
                    *(__nv_bfloat162*)(g_AB + (size_t)r * 512 + c_off + col) = hv;
                } else if (c_sel == 5) {
                    __nv_bfloat162 hv = __float22bfloat162_rn(make_float2(vx, vy));
                    *(__nv_bfloat162*)(g_xwb + (size_t)r * HD + col) = hv;
                } else {
                    *(float2*)(buf_sel(c_sel) + (size_t)r * ldc + c_off + col) = make_float2(vx, vy);
                }
                if (agg_sel) {
                    float dv = g_dinv[r]; dv *= dv;
                    float2 w;
                    w.x = fmaf(vx, dv, bias[col]);
                    w.y = fmaf(vy, dv, bias[col + 1]);
                    *(float2*)(Cagg + (size_t)r * HD + col) = w;
                }
            }
        }
    }
}

// ---------------- edge MLP: out[e] = sigmoid( relu(AB_A[s]+AB_B[d]+bm1) . Wm2 + bm2 ) ----------------
__global__ __launch_bounds__(256) void k_edge_mlp(const int* __restrict__ src,
                                                  const int* __restrict__ dst,
                                                  const float* __restrict__ bm1,
                                                  const float* __restrict__ Wm2,
                                                  const float* __restrict__ bm2,
                                                  float* __restrict__ out, int e) {
    __shared__ __align__(16) float w[HD];
    __shared__ __align__(16) float b[HD];
    int tid = threadIdx.x;
    w[tid] = Wm2[tid];
    b[tid] = bm1[tid];
    __syncthreads();
    int ei = blockIdx.x * 8 + (tid >> 5);
    if (ei >= e) return;
    int lane = tid & 31;
    int s = src[ei], d = dst[ei];
    const __nv_bfloat16* pa = g_AB + (size_t)s * 512;
    const __nv_bfloat16* pb = g_AB + (size_t)d * 512 + HD;
    float acc = 0.f;
#pragma unroll
    for (int it = 0; it < 2; it++) {
        int j = (it * 32 + lane) << 2;
        float4 va = ldbf4(pa + j);
        float4 vb = ldbf4(pb + j);
        float4 vbi = *(const float4*)(b + j);
        float4 vw = *(const float4*)(w + j);
        acc += fmaxf(va.x + vb.x + vbi.x, 0.f) * vw.x;
        acc += fmaxf(va.y + vb.y + vbi.y, 0.f) * vw.y;
        acc += fmaxf(va.z + vb.z + vbi.z, 0.f) * vw.z;
        acc += fmaxf(va.w + vb.w + vbi.w, 0.f) * vw.w;
    }
#pragma unroll
    for (int o = 16; o; o >>= 1) acc += __shfl_xor_sync(0xffffffffu, acc, o);
    if (lane == 0) {
        float z = acc + bm2[0];
        out[ei] = 1.0f / (1.0f + expf(-z));
    }
}

// ---------------- launch ----------------
extern "C" void kernel_launch(void* const* d_in, const int* in_sizes, int n_in,
                              void* d_out, int out_size) {
    const float* x    = (const float*)d_in[0];
    const int*   ei   = (const int*)d_in[1];     // edge_index delivered as int32
    const float* W1   = (const float*)d_in[2];
    const float* b1   = (const float*)d_in[3];
    const float* gamma= (const float*)d_in[4];
    const float* beta = (const float*)d_in[5];
    const float* W2   = (const float*)d_in[6];
    const float* b2   = (const float*)d_in[7];
    const float* Wm1  = (const float*)d_in[8];
    const float* bm1  = (const float*)d_in[9];
    const float* Wm2  = (const float*)d_in[10];
    const float* bm2  = (const float*)d_in[11];
    float* out = (float*)d_out;

    const int n = in_sizes[0] / 128;      // 50000
    const int e = in_sizes[1] / 2;        // 400000
    const int* src = ei;
    const int* dst = ei + e;

    // 1. degrees / norm
    k_init<<<(n + 255) / 256, 256>>>(n);
    k_deg_edges<<<(e + 255) / 256, 256>>>(dst, e);
    k_dinv<<<(n + 255) / 256, 256>>>(n);

    dim3 g1(HD / 64, (n + 127) / 128);    // 4 x 391

    // 2. gcn1: g_xwb = bf16(x@W1), fused agg-init -> buf2 ; edge agg g_xwb -> buf2
    k_gemm<<<g1, 256>>>(x, 0, 0, W1, 5, 0, HD, 2, b1, n, 128, HD);
    k_edge_agg<<<(e * 64 + 255) / 256, 256>>>(src, dst, 2, e);

    // 3. batchnorm stats (apply is fused into the next GEMM's A-load)
    k_bn_stats<<<512, 256>>>(n);
    k_bn_finalize<<<1, 256>>>(gamma, beta, n);

    // 4. gcn2: g_xwb = bf16(bn_relu(buf2)@W2), fused agg-init -> buf3 ; edge agg g_xwb -> buf3
    k_gemm<<<g1, 256>>>(nullptr, 2, 2, W2, 5, 0, HD, 4, b2, n, HD, HD);
    k_edge_agg<<<(e * 64 + 255) / 256, 256>>>(src, dst, 4, e);

    // 5. hoisted MLP layer 1 (relu fused into A-load, bf16 output into g_AB):
    k_gemm<<<g1, 256>>>(nullptr, 4, 1, Wm1,            3, 0,  512, 0, nullptr, n, HD, HD);
    k_gemm<<<g1, 256>>>(nullptr, 4, 1, Wm1 + 256 * HD, 3, HD, 512, 0, nullptr, n, HD, HD);

    // 6. per-edge epilogue (bf16 gathers)
    k_edge_mlp<<<(e + 7) / 8, 256>>>(src, dst, bm1, Wm2, bm2, out, e);
}